// round 5
// baseline (speedup 1.0000x reference)
#include <cuda_runtime.h>

// ---------------------------------------------------------------------------
// GAT 2-layer forward, fixed shapes:
//   N=100000 nodes, Fin=256, layer1: H=4 x C=32 (F1=128, concat),
//   layer2: H=1 x C=64, E=1.6M edges + N self loops.
// Pipeline (fp32, default stream, graph-capturable, no allocations):
//   prep edges -> init -> gemm1 -> att1 -> edge max/sum/agg (L1) -> ELU ->
//   gemm2 -> att2 -> edge max/sum/agg (L2, into d_out preloaded with bias)
// ---------------------------------------------------------------------------

#define NNODES 100000
#define E_IN   1600000
#define ETOT   (E_IN + NNODES)
#define NH1    4
#define F1     128
#define FIN    256
#define CO     64
#define EPSV   1e-16f

static const int TPB = 256;

// ---------------- device scratch (static, 16B-aligned) ----------------------
__device__ __align__(16) float    g_h1  [(size_t)NNODES * F1];
__device__ __align__(16) float    g_agg1[(size_t)NNODES * F1];
__device__ __align__(16) float    g_h2  [(size_t)NNODES * CO];
__device__ __align__(16) float    g_asrc1[NNODES * NH1];
__device__ __align__(16) float    g_adst1[NNODES * NH1];
__device__ __align__(16) unsigned g_m1  [NNODES * NH1];
__device__ __align__(16) float    g_den1[NNODES * NH1];
__device__ __align__(16) float    g_ex1 [(size_t)ETOT * NH1];
__device__ __align__(16) float    g_asrc2[NNODES];
__device__ __align__(16) float    g_adst2[NNODES];
__device__ __align__(16) unsigned g_m2  [NNODES];
__device__ __align__(16) float    g_den2[NNODES];
__device__ __align__(16) float    g_ex2 [ETOT];
__device__ int g_src[ETOT];
__device__ int g_dst[ETOT];

// ---------------- helpers ----------------------------------------------------
__device__ __forceinline__ unsigned fenc(float f) {
    unsigned u = __float_as_uint(f);
    return (u & 0x80000000u) ? ~u : (u | 0x80000000u);
}
__device__ __forceinline__ float fdec(unsigned u) {
    return __uint_as_float((u & 0x80000000u) ? (u ^ 0x80000000u) : ~u);
}
__device__ __forceinline__ float lrelu(float v) { return v >= 0.f ? v : 0.2f * v; }

// ---------------- edge prep: dtype-robust decode -----------------------------
// Reference declares edge_index int64, but JAX default x64=off silently yields
// int32. Detect on-device: first 4 values read as int64 are all in [0,N) iff
// the data really is int64 (int32 data read as int64 packs a random nonzero
// index into the high word).
__global__ void k_prep_edges(const void* __restrict__ ei_raw) {
    int e = blockIdx.x * blockDim.x + threadIdx.x;
    if (e >= ETOT) return;
    if (e >= E_IN) { int v = e - E_IN; g_src[e] = v; g_dst[e] = v; return; }
    const long long* e64 = (const long long*)ei_raw;
    bool is64 = true;
#pragma unroll
    for (int q = 0; q < 4; q++) {
        long long v = e64[q];
        if (v < 0 || v >= NNODES) is64 = false;
    }
    int s, d;
    if (is64) {
        s = (int)e64[e];
        d = (int)e64[(size_t)E_IN + e];
    } else {
        const int* e32 = (const int*)ei_raw;
        s = e32[e];
        d = e32[E_IN + e];
    }
    g_src[e] = s;
    g_dst[e] = d;
}

// ---------------- init --------------------------------------------------------
__global__ void k_init_stats() {
    int i = blockIdx.x * blockDim.x + threadIdx.x;
    if (i < NNODES * NH1) { g_m1[i] = 0u; g_den1[i] = 0.f; }
    if (i < NNODES)       { g_m2[i] = 0u; g_den2[i] = 0.f; }
}
__global__ void k_init_agg(const float* __restrict__ b1,
                           const float* __restrict__ b2,
                           float* __restrict__ out) {
    int i = blockIdx.x * blockDim.x + threadIdx.x;
    if (i < NNODES * F1) g_agg1[i] = b1[i & (F1 - 1)];
    if (i < NNODES * CO) out[i]    = b2[i & (CO - 1)];
}

// ---------------- fp32 tiled GEMM: C[M,BN] = A[M,K] @ B[K,BN] -----------------
// BM=64, BK=16, 256 threads, micro-tile 4 x TN per thread (16x16 thread grid).
template <int BN, int TN, int K>
__device__ __forceinline__ void gemm_body(const float* __restrict__ A,
                                          const float* __restrict__ B,
                                          float* __restrict__ C, int M) {
    __shared__ float As[16][64];
    __shared__ float Bs[16][BN];
    const int tid  = threadIdx.x;
    const int tx   = tid & 15;
    const int ty   = tid >> 4;
    const int row0 = blockIdx.x * 64;

    float acc[4][TN];
#pragma unroll
    for (int i = 0; i < 4; i++)
#pragma unroll
        for (int j = 0; j < TN; j++) acc[i][j] = 0.f;

    const int a_row = tid >> 2;         // 0..63
    const int a_col = (tid & 3) << 2;   // 0,4,8,12

    for (int k0 = 0; k0 < K; k0 += 16) {
        float4 av = make_float4(0.f, 0.f, 0.f, 0.f);
        int gr = row0 + a_row;
        if (gr < M) av = *(const float4*)&A[(size_t)gr * K + k0 + a_col];
        As[a_col + 0][a_row] = av.x;
        As[a_col + 1][a_row] = av.y;
        As[a_col + 2][a_row] = av.z;
        As[a_col + 3][a_row] = av.w;
#pragma unroll
        for (int p = 0; p < BN / 64; p++) {
            int idx = tid + p * 256;
            int br  = idx / (BN / 4);
            int bc  = (idx % (BN / 4)) * 4;
            *(float4*)&Bs[br][bc] = *(const float4*)&B[(size_t)(k0 + br) * BN + bc];
        }
        __syncthreads();
#pragma unroll
        for (int kk = 0; kk < 16; kk++) {
            float4 a4 = *(const float4*)&As[kk][ty * 4];
            float aa[4] = {a4.x, a4.y, a4.z, a4.w};
            float bb[TN];
#pragma unroll
            for (int jj = 0; jj < TN / 4; jj++) {
                float4 b4 = *(const float4*)&Bs[kk][tx * TN + jj * 4];
                bb[jj * 4 + 0] = b4.x; bb[jj * 4 + 1] = b4.y;
                bb[jj * 4 + 2] = b4.z; bb[jj * 4 + 3] = b4.w;
            }
#pragma unroll
            for (int i = 0; i < 4; i++)
#pragma unroll
                for (int j = 0; j < TN; j++)
                    acc[i][j] = fmaf(aa[i], bb[j], acc[i][j]);
        }
        __syncthreads();
    }
#pragma unroll
    for (int i = 0; i < 4; i++) {
        int gr = row0 + ty * 4 + i;
        if (gr < M) {
#pragma unroll
            for (int jj = 0; jj < TN / 4; jj++) {
                float4 v = make_float4(acc[i][jj * 4 + 0], acc[i][jj * 4 + 1],
                                       acc[i][jj * 4 + 2], acc[i][jj * 4 + 3]);
                *(float4*)&C[(size_t)gr * BN + tx * TN + jj * 4] = v;
            }
        }
    }
}

__global__ void __launch_bounds__(256) gemm1_kernel(const float* __restrict__ x,
                                                    const float* __restrict__ W1) {
    gemm_body<F1, 8, FIN>(x, W1, g_h1, NNODES);
}
__global__ void __launch_bounds__(256) gemm2_kernel(const float* __restrict__ W2) {
    gemm_body<CO, 4, F1>(g_agg1, W2, g_h2, NNODES);
}

// ---------------- attention coefficients --------------------------------------
__global__ void k_att1(const float* __restrict__ att_s,
                       const float* __restrict__ att_d) {
    __shared__ float ss[F1], sd[F1];
    if (threadIdx.x < F1) { ss[threadIdx.x] = att_s[threadIdx.x];
                            sd[threadIdx.x] = att_d[threadIdx.x]; }
    __syncthreads();
    int i = blockIdx.x * blockDim.x + threadIdx.x;
    if (i >= NNODES * NH1) return;
    int n = i >> 2, h = i & 3;
    const float4* hv = (const float4*)&g_h1[(size_t)n * F1 + h * 32];
    const float4* sv = (const float4*)&ss[h * 32];
    const float4* dv = (const float4*)&sd[h * 32];
    float s = 0.f, d = 0.f;
#pragma unroll
    for (int q = 0; q < 8; q++) {
        float4 hh = hv[q], a = sv[q], b = dv[q];
        s += hh.x * a.x + hh.y * a.y + hh.z * a.z + hh.w * a.w;
        d += hh.x * b.x + hh.y * b.y + hh.z * b.z + hh.w * b.w;
    }
    g_asrc1[i] = s;
    g_adst1[i] = d;
}

__global__ void k_att2(const float* __restrict__ att_s,
                       const float* __restrict__ att_d) {
    __shared__ float ss[CO], sd[CO];
    if (threadIdx.x < CO) { ss[threadIdx.x] = att_s[threadIdx.x];
                            sd[threadIdx.x] = att_d[threadIdx.x]; }
    __syncthreads();
    int n = blockIdx.x * blockDim.x + threadIdx.x;
    if (n >= NNODES) return;
    const float4* hv = (const float4*)&g_h2[(size_t)n * CO];
    const float4* sv = (const float4*)ss;
    const float4* dv = (const float4*)sd;
    float s = 0.f, d = 0.f;
#pragma unroll
    for (int q = 0; q < CO / 4; q++) {
        float4 hh = hv[q], a = sv[q], b = dv[q];
        s += hh.x * a.x + hh.y * a.y + hh.z * a.z + hh.w * a.w;
        d += hh.x * b.x + hh.y * b.y + hh.z * b.z + hh.w * b.w;
    }
    g_asrc2[n] = s;
    g_adst2[n] = d;
}

// ---------------- layer-1 edge passes ------------------------------------------
__global__ void k_edge_max1() {
    int e = blockIdx.x * blockDim.x + threadIdx.x;
    if (e >= ETOT) return;
    int s = g_src[e], d = g_dst[e];
    float4 as = *(const float4*)&g_asrc1[s * 4];
    float4 ad = *(const float4*)&g_adst1[d * 4];
    atomicMax(&g_m1[d * 4 + 0], fenc(lrelu(as.x + ad.x)));
    atomicMax(&g_m1[d * 4 + 1], fenc(lrelu(as.y + ad.y)));
    atomicMax(&g_m1[d * 4 + 2], fenc(lrelu(as.z + ad.z)));
    atomicMax(&g_m1[d * 4 + 3], fenc(lrelu(as.w + ad.w)));
}

__global__ void k_edge_sum1() {
    int e = blockIdx.x * blockDim.x + threadIdx.x;
    if (e >= ETOT) return;
    int s = g_src[e], d = g_dst[e];
    float4 as = *(const float4*)&g_asrc1[s * 4];
    float4 ad = *(const float4*)&g_adst1[d * 4];
    uint4  mu = *(const uint4*)&g_m1[d * 4];
    float e0 = expf(lrelu(as.x + ad.x) - fdec(mu.x));
    float e1 = expf(lrelu(as.y + ad.y) - fdec(mu.y));
    float e2 = expf(lrelu(as.z + ad.z) - fdec(mu.z));
    float e3 = expf(lrelu(as.w + ad.w) - fdec(mu.w));
    *(float4*)&g_ex1[(size_t)e * 4] = make_float4(e0, e1, e2, e3);
    atomicAdd(&g_den1[d * 4 + 0], e0);
    atomicAdd(&g_den1[d * 4 + 1], e1);
    atomicAdd(&g_den1[d * 4 + 2], e2);
    atomicAdd(&g_den1[d * 4 + 3], e3);
}

// warp per edge: lane l handles features [4l, 4l+4); head = lane/8
__global__ void k_edge_agg1() {
    long long t = (long long)blockIdx.x * blockDim.x + threadIdx.x;
    int e = (int)(t >> 5);
    if (e >= ETOT) return;
    int lane = threadIdx.x & 31;
    int s = g_src[e], d = g_dst[e];
    int h = lane >> 3;
    float alpha = g_ex1[(size_t)e * 4 + h] / (g_den1[d * 4 + h] + EPSV);
    float4 hv = *(const float4*)&g_h1[(size_t)s * F1 + lane * 4];
    float* o = &g_agg1[(size_t)d * F1 + lane * 4];
    atomicAdd(o + 0, hv.x * alpha);
    atomicAdd(o + 1, hv.y * alpha);
    atomicAdd(o + 2, hv.z * alpha);
    atomicAdd(o + 3, hv.w * alpha);
}

__global__ void k_elu() {
    int i = blockIdx.x * blockDim.x + threadIdx.x;
    if (i >= NNODES * F1) return;
    float v = g_agg1[i];
    g_agg1[i] = v > 0.f ? v : expm1f(v);
}

// ---------------- layer-2 edge passes ------------------------------------------
__global__ void k_edge_max2() {
    int e = blockIdx.x * blockDim.x + threadIdx.x;
    if (e >= ETOT) return;
    int s = g_src[e], d = g_dst[e];
    atomicMax(&g_m2[d], fenc(lrelu(g_asrc2[s] + g_adst2[d])));
}

__global__ void k_edge_sum2() {
    int e = blockIdx.x * blockDim.x + threadIdx.x;
    if (e >= ETOT) return;
    int s = g_src[e], d = g_dst[e];
    float v  = lrelu(g_asrc2[s] + g_adst2[d]);
    float ex = expf(v - fdec(g_m2[d]));
    g_ex2[e] = ex;
    atomicAdd(&g_den2[d], ex);
}

// warp per edge: lane l handles features [2l, 2l+2)
__global__ void k_edge_agg2(float* __restrict__ out) {
    long long t = (long long)blockIdx.x * blockDim.x + threadIdx.x;
    int e = (int)(t >> 5);
    if (e >= ETOT) return;
    int lane = threadIdx.x & 31;
    int s = g_src[e], d = g_dst[e];
    float alpha = g_ex2[e] / (g_den2[d] + EPSV);
    float2 hv = *(const float2*)&g_h2[(size_t)s * CO + lane * 2];
    atomicAdd(&out[(size_t)d * CO + lane * 2 + 0], hv.x * alpha);
    atomicAdd(&out[(size_t)d * CO + lane * 2 + 1], hv.y * alpha);
}

// ---------------- launcher -------------------------------------------------------
extern "C" void kernel_launch(void* const* d_in, const int* in_sizes, int n_in,
                              void* d_out, int out_size) {
    const float* x   = (const float*)d_in[0];
    const void*  ei  = d_in[1];
    const float* W1  = (const float*)d_in[2];
    const float* as1 = (const float*)d_in[3];
    const float* ad1 = (const float*)d_in[4];
    const float* b1  = (const float*)d_in[5];
    const float* W2  = (const float*)d_in[6];
    const float* as2 = (const float*)d_in[7];
    const float* ad2 = (const float*)d_in[8];
    const float* b2  = (const float*)d_in[9];
    float* out = (float*)d_out;

    (void)in_sizes; (void)n_in; (void)out_size;

    const int gStats = (NNODES * NH1 + TPB - 1) / TPB;
    const int gAgg   = (NNODES * F1 + TPB - 1) / TPB;
    const int gGemm  = (NNODES + 63) / 64;
    const int gEdge  = (ETOT + TPB - 1) / TPB;
    const int gEdgeW = (int)(((long long)ETOT * 32 + TPB - 1) / TPB);
    const int gNode  = (NNODES + TPB - 1) / TPB;

    k_prep_edges<<<gEdge, TPB>>>(ei);
    k_init_stats<<<gStats, TPB>>>();
    k_init_agg<<<gAgg, TPB>>>(b1, b2, out);

    gemm1_kernel<<<gGemm, TPB>>>(x, W1);
    k_att1<<<gStats, TPB>>>(as1, ad1);

    k_edge_max1<<<gEdge, TPB>>>();
    k_edge_sum1<<<gEdge, TPB>>>();
    k_edge_agg1<<<gEdgeW, TPB>>>();

    k_elu<<<gAgg, TPB>>>();
    gemm2_kernel<<<gGemm, TPB>>>(W2);
    k_att2<<<gNode, TPB>>>(as2, ad2);

    k_edge_max2<<<gEdge, TPB>>>();
    k_edge_sum2<<<gEdge, TPB>>>();
    k_edge_agg2<<<gEdgeW, TPB>>>(out);
}

// round 6
// speedup vs baseline: 1.0001x; 1.0001x over previous
#include <cuda_runtime.h>

// ---------------------------------------------------------------------------
// GAT 2-layer forward, fixed shapes:
//   N=100000 nodes, Fin=256, layer1: H=4 x C=32 (F1=128, concat),
//   layer2: H=1 x C=64, E=1.6M edges + N self loops.
// Pipeline (fp32, default stream, graph-capturable, no allocations):
//   prep edges -> init -> gemm1 -> att1 -> edge max/sum/agg (L1) -> ELU ->
//   gemm2 -> att2 -> edge max/sum/agg (L2, into d_out preloaded with bias)
// ---------------------------------------------------------------------------

#define NNODES 100000
#define E_IN   1600000
#define ETOT   (E_IN + NNODES)
#define NH1    4
#define F1     128
#define FIN    256
#define CO     64
#define EPSV   1e-16f

static const int TPB = 256;

// ---------------- device scratch (static, 16B-aligned) ----------------------
__device__ __align__(16) float    g_h1  [(size_t)NNODES * F1];
__device__ __align__(16) float    g_agg1[(size_t)NNODES * F1];
__device__ __align__(16) float    g_h2  [(size_t)NNODES * CO];
__device__ __align__(16) float    g_asrc1[NNODES * NH1];
__device__ __align__(16) float    g_adst1[NNODES * NH1];
__device__ __align__(16) unsigned g_m1  [NNODES * NH1];
__device__ __align__(16) float    g_den1[NNODES * NH1];
__device__ __align__(16) float    g_ex1 [(size_t)ETOT * NH1];
__device__ __align__(16) float    g_asrc2[NNODES];
__device__ __align__(16) float    g_adst2[NNODES];
__device__ __align__(16) unsigned g_m2  [NNODES];
__device__ __align__(16) float    g_den2[NNODES];
__device__ __align__(16) float    g_ex2 [ETOT];
__device__ int g_src[ETOT];
__device__ int g_dst[ETOT];

// ---------------- helpers ----------------------------------------------------
__device__ __forceinline__ unsigned fenc(float f) {
    unsigned u = __float_as_uint(f);
    return (u & 0x80000000u) ? ~u : (u | 0x80000000u);
}
__device__ __forceinline__ float fdec(unsigned u) {
    return __uint_as_float((u & 0x80000000u) ? (u ^ 0x80000000u) : ~u);
}
__device__ __forceinline__ float lrelu(float v) { return v >= 0.f ? v : 0.2f * v; }

// ---------------- edge prep: dtype-robust decode -----------------------------
// Reference declares edge_index int64, but JAX default x64=off silently yields
// int32. Detect on-device: first 4 values read as int64 are all in [0,N) iff
// the data really is int64 (int32 data read as int64 packs a random nonzero
// index into the high word).
__global__ void k_prep_edges(const void* __restrict__ ei_raw) {
    int e = blockIdx.x * blockDim.x + threadIdx.x;
    if (e >= ETOT) return;
    if (e >= E_IN) { int v = e - E_IN; g_src[e] = v; g_dst[e] = v; return; }
    const long long* e64 = (const long long*)ei_raw;
    bool is64 = true;
#pragma unroll
    for (int q = 0; q < 4; q++) {
        long long v = e64[q];
        if (v < 0 || v >= NNODES) is64 = false;
    }
    int s, d;
    if (is64) {
        s = (int)e64[e];
        d = (int)e64[(size_t)E_IN + e];
    } else {
        const int* e32 = (const int*)ei_raw;
        s = e32[e];
        d = e32[E_IN + e];
    }
    g_src[e] = s;
    g_dst[e] = d;
}

// ---------------- init --------------------------------------------------------
__global__ void k_init_stats() {
    int i = blockIdx.x * blockDim.x + threadIdx.x;
    if (i < NNODES * NH1) { g_m1[i] = 0u; g_den1[i] = 0.f; }
    if (i < NNODES)       { g_m2[i] = 0u; g_den2[i] = 0.f; }
}
__global__ void k_init_agg(const float* __restrict__ b1,
                           const float* __restrict__ b2,
                           float* __restrict__ out) {
    int i = blockIdx.x * blockDim.x + threadIdx.x;
    if (i < NNODES * F1) g_agg1[i] = b1[i & (F1 - 1)];
    if (i < NNODES * CO) out[i]    = b2[i & (CO - 1)];
}

// ---------------- fp32 tiled GEMM: C[M,BN] = A[M,K] @ B[K,BN] -----------------
// BM=64, BK=16, 256 threads, micro-tile 4 x TN per thread (16x16 thread grid).
template <int BN, int TN, int K>
__device__ __forceinline__ void gemm_body(const float* __restrict__ A,
                                          const float* __restrict__ B,
                                          float* __restrict__ C, int M) {
    __shared__ float As[16][64];
    __shared__ float Bs[16][BN];
    const int tid  = threadIdx.x;
    const int tx   = tid & 15;
    const int ty   = tid >> 4;
    const int row0 = blockIdx.x * 64;

    float acc[4][TN];
#pragma unroll
    for (int i = 0; i < 4; i++)
#pragma unroll
        for (int j = 0; j < TN; j++) acc[i][j] = 0.f;

    const int a_row = tid >> 2;         // 0..63
    const int a_col = (tid & 3) << 2;   // 0,4,8,12

    for (int k0 = 0; k0 < K; k0 += 16) {
        float4 av = make_float4(0.f, 0.f, 0.f, 0.f);
        int gr = row0 + a_row;
        if (gr < M) av = *(const float4*)&A[(size_t)gr * K + k0 + a_col];
        As[a_col + 0][a_row] = av.x;
        As[a_col + 1][a_row] = av.y;
        As[a_col + 2][a_row] = av.z;
        As[a_col + 3][a_row] = av.w;
#pragma unroll
        for (int p = 0; p < BN / 64; p++) {
            int idx = tid + p * 256;
            int br  = idx / (BN / 4);
            int bc  = (idx % (BN / 4)) * 4;
            *(float4*)&Bs[br][bc] = *(const float4*)&B[(size_t)(k0 + br) * BN + bc];
        }
        __syncthreads();
#pragma unroll
        for (int kk = 0; kk < 16; kk++) {
            float4 a4 = *(const float4*)&As[kk][ty * 4];
            float aa[4] = {a4.x, a4.y, a4.z, a4.w};
            float bb[TN];
#pragma unroll
            for (int jj = 0; jj < TN / 4; jj++) {
                float4 b4 = *(const float4*)&Bs[kk][tx * TN + jj * 4];
                bb[jj * 4 + 0] = b4.x; bb[jj * 4 + 1] = b4.y;
                bb[jj * 4 + 2] = b4.z; bb[jj * 4 + 3] = b4.w;
            }
#pragma unroll
            for (int i = 0; i < 4; i++)
#pragma unroll
                for (int j = 0; j < TN; j++)
                    acc[i][j] = fmaf(aa[i], bb[j], acc[i][j]);
        }
        __syncthreads();
    }
#pragma unroll
    for (int i = 0; i < 4; i++) {
        int gr = row0 + ty * 4 + i;
        if (gr < M) {
#pragma unroll
            for (int jj = 0; jj < TN / 4; jj++) {
                float4 v = make_float4(acc[i][jj * 4 + 0], acc[i][jj * 4 + 1],
                                       acc[i][jj * 4 + 2], acc[i][jj * 4 + 3]);
                *(float4*)&C[(size_t)gr * BN + tx * TN + jj * 4] = v;
            }
        }
    }
}

__global__ void __launch_bounds__(256) gemm1_kernel(const float* __restrict__ x,
                                                    const float* __restrict__ W1) {
    gemm_body<F1, 8, FIN>(x, W1, g_h1, NNODES);
}
__global__ void __launch_bounds__(256) gemm2_kernel(const float* __restrict__ W2) {
    gemm_body<CO, 4, F1>(g_agg1, W2, g_h2, NNODES);
}

// ---------------- attention coefficients --------------------------------------
__global__ void k_att1(const float* __restrict__ att_s,
                       const float* __restrict__ att_d) {
    __shared__ float ss[F1], sd[F1];
    if (threadIdx.x < F1) { ss[threadIdx.x] = att_s[threadIdx.x];
                            sd[threadIdx.x] = att_d[threadIdx.x]; }
    __syncthreads();
    int i = blockIdx.x * blockDim.x + threadIdx.x;
    if (i >= NNODES * NH1) return;
    int n = i >> 2, h = i & 3;
    const float4* hv = (const float4*)&g_h1[(size_t)n * F1 + h * 32];
    const float4* sv = (const float4*)&ss[h * 32];
    const float4* dv = (const float4*)&sd[h * 32];
    float s = 0.f, d = 0.f;
#pragma unroll
    for (int q = 0; q < 8; q++) {
        float4 hh = hv[q], a = sv[q], b = dv[q];
        s += hh.x * a.x + hh.y * a.y + hh.z * a.z + hh.w * a.w;
        d += hh.x * b.x + hh.y * b.y + hh.z * b.z + hh.w * b.w;
    }
    g_asrc1[i] = s;
    g_adst1[i] = d;
}

__global__ void k_att2(const float* __restrict__ att_s,
                       const float* __restrict__ att_d) {
    __shared__ float ss[CO], sd[CO];
    if (threadIdx.x < CO) { ss[threadIdx.x] = att_s[threadIdx.x];
                            sd[threadIdx.x] = att_d[threadIdx.x]; }
    __syncthreads();
    int n = blockIdx.x * blockDim.x + threadIdx.x;
    if (n >= NNODES) return;
    const float4* hv = (const float4*)&g_h2[(size_t)n * CO];
    const float4* sv = (const float4*)ss;
    const float4* dv = (const float4*)sd;
    float s = 0.f, d = 0.f;
#pragma unroll
    for (int q = 0; q < CO / 4; q++) {
        float4 hh = hv[q], a = sv[q], b = dv[q];
        s += hh.x * a.x + hh.y * a.y + hh.z * a.z + hh.w * a.w;
        d += hh.x * b.x + hh.y * b.y + hh.z * b.z + hh.w * b.w;
    }
    g_asrc2[n] = s;
    g_adst2[n] = d;
}

// ---------------- layer-1 edge passes ------------------------------------------
__global__ void k_edge_max1() {
    int e = blockIdx.x * blockDim.x + threadIdx.x;
    if (e >= ETOT) return;
    int s = g_src[e], d = g_dst[e];
    float4 as = *(const float4*)&g_asrc1[s * 4];
    float4 ad = *(const float4*)&g_adst1[d * 4];
    atomicMax(&g_m1[d * 4 + 0], fenc(lrelu(as.x + ad.x)));
    atomicMax(&g_m1[d * 4 + 1], fenc(lrelu(as.y + ad.y)));
    atomicMax(&g_m1[d * 4 + 2], fenc(lrelu(as.z + ad.z)));
    atomicMax(&g_m1[d * 4 + 3], fenc(lrelu(as.w + ad.w)));
}

__global__ void k_edge_sum1() {
    int e = blockIdx.x * blockDim.x + threadIdx.x;
    if (e >= ETOT) return;
    int s = g_src[e], d = g_dst[e];
    float4 as = *(const float4*)&g_asrc1[s * 4];
    float4 ad = *(const float4*)&g_adst1[d * 4];
    uint4  mu = *(const uint4*)&g_m1[d * 4];
    float e0 = expf(lrelu(as.x + ad.x) - fdec(mu.x));
    float e1 = expf(lrelu(as.y + ad.y) - fdec(mu.y));
    float e2 = expf(lrelu(as.z + ad.z) - fdec(mu.z));
    float e3 = expf(lrelu(as.w + ad.w) - fdec(mu.w));
    *(float4*)&g_ex1[(size_t)e * 4] = make_float4(e0, e1, e2, e3);
    atomicAdd(&g_den1[d * 4 + 0], e0);
    atomicAdd(&g_den1[d * 4 + 1], e1);
    atomicAdd(&g_den1[d * 4 + 2], e2);
    atomicAdd(&g_den1[d * 4 + 3], e3);
}

// warp per edge: lane l handles features [4l, 4l+4); head = lane/8
__global__ void k_edge_agg1() {
    long long t = (long long)blockIdx.x * blockDim.x + threadIdx.x;
    int e = (int)(t >> 5);
    if (e >= ETOT) return;
    int lane = threadIdx.x & 31;
    int s = g_src[e], d = g_dst[e];
    int h = lane >> 3;
    float alpha = g_ex1[(size_t)e * 4 + h] / (g_den1[d * 4 + h] + EPSV);
    float4 hv = *(const float4*)&g_h1[(size_t)s * F1 + lane * 4];
    float* o = &g_agg1[(size_t)d * F1 + lane * 4];
    atomicAdd(o + 0, hv.x * alpha);
    atomicAdd(o + 1, hv.y * alpha);
    atomicAdd(o + 2, hv.z * alpha);
    atomicAdd(o + 3, hv.w * alpha);
}

__global__ void k_elu() {
    int i = blockIdx.x * blockDim.x + threadIdx.x;
    if (i >= NNODES * F1) return;
    float v = g_agg1[i];
    g_agg1[i] = v > 0.f ? v : expm1f(v);
}

// ---------------- layer-2 edge passes ------------------------------------------
__global__ void k_edge_max2() {
    int e = blockIdx.x * blockDim.x + threadIdx.x;
    if (e >= ETOT) return;
    int s = g_src[e], d = g_dst[e];
    atomicMax(&g_m2[d], fenc(lrelu(g_asrc2[s] + g_adst2[d])));
}

__global__ void k_edge_sum2() {
    int e = blockIdx.x * blockDim.x + threadIdx.x;
    if (e >= ETOT) return;
    int s = g_src[e], d = g_dst[e];
    float v  = lrelu(g_asrc2[s] + g_adst2[d]);
    float ex = expf(v - fdec(g_m2[d]));
    g_ex2[e] = ex;
    atomicAdd(&g_den2[d], ex);
}

// warp per edge: lane l handles features [2l, 2l+2)
__global__ void k_edge_agg2(float* __restrict__ out) {
    long long t = (long long)blockIdx.x * blockDim.x + threadIdx.x;
    int e = (int)(t >> 5);
    if (e >= ETOT) return;
    int lane = threadIdx.x & 31;
    int s = g_src[e], d = g_dst[e];
    float alpha = g_ex2[e] / (g_den2[d] + EPSV);
    float2 hv = *(const float2*)&g_h2[(size_t)s * CO + lane * 2];
    atomicAdd(&out[(size_t)d * CO + lane * 2 + 0], hv.x * alpha);
    atomicAdd(&out[(size_t)d * CO + lane * 2 + 1], hv.y * alpha);
}

// ---------------- launcher -------------------------------------------------------
extern "C" void kernel_launch(void* const* d_in, const int* in_sizes, int n_in,
                              void* d_out, int out_size) {
    const float* x   = (const float*)d_in[0];
    const void*  ei  = d_in[1];
    const float* W1  = (const float*)d_in[2];
    const float* as1 = (const float*)d_in[3];
    const float* ad1 = (const float*)d_in[4];
    const float* b1  = (const float*)d_in[5];
    const float* W2  = (const float*)d_in[6];
    const float* as2 = (const float*)d_in[7];
    const float* ad2 = (const float*)d_in[8];
    const float* b2  = (const float*)d_in[9];
    float* out = (float*)d_out;

    (void)in_sizes; (void)n_in; (void)out_size;

    const int gStats = (NNODES * NH1 + TPB - 1) / TPB;
    const int gAgg   = (NNODES * F1 + TPB - 1) / TPB;
    const int gGemm  = (NNODES + 63) / 64;
    const int gEdge  = (ETOT + TPB - 1) / TPB;
    const int gEdgeW = (int)(((long long)ETOT * 32 + TPB - 1) / TPB);
    const int gNode  = (NNODES + TPB - 1) / TPB;

    k_prep_edges<<<gEdge, TPB>>>(ei);
    k_init_stats<<<gStats, TPB>>>();
    k_init_agg<<<gAgg, TPB>>>(b1, b2, out);

    gemm1_kernel<<<gGemm, TPB>>>(x, W1);
    k_att1<<<gStats, TPB>>>(as1, ad1);

    k_edge_max1<<<gEdge, TPB>>>();
    k_edge_sum1<<<gEdge, TPB>>>();
    k_edge_agg1<<<gEdgeW, TPB>>>();

    k_elu<<<gAgg, TPB>>>();
    gemm2_kernel<<<gGemm, TPB>>>(W2);
    k_att2<<<gNode, TPB>>>(as2, ad2);

    k_edge_max2<<<gEdge, TPB>>>();
    k_edge_sum2<<<gEdge, TPB>>>();
    k_edge_agg2<<<gEdgeW, TPB>>>(out);
}

// round 7
// speedup vs baseline: 2.7091x; 2.7087x over previous
#include <cuda_runtime.h>
#include <math_constants.h>

// ---------------------------------------------------------------------------
// GAT 2-layer forward, fixed shapes. CSR-based, zero float atomics.
//   N=100000, Fin=256, L1: H=4 x C=32 (F1=128 concat), L2: 1 x 64.
//   E=1.6M + N self loops.
// Pipeline: decode+histogram -> scan(3) -> scatter ->
//           gemm1(128x128 tile) -> att1 -> fused softmax+agg L1 (+bias+ELU) ->
//           gemm2 -> att2 -> fused softmax+agg L2 (+bias) -> out
// ---------------------------------------------------------------------------

#define NNODES 100000
#define E_IN   1600000
#define ETOT   (E_IN + NNODES)
#define NH1    4
#define F1     128
#define FIN    256
#define CO     64
#define EPSV   1e-16f
#define SCAN_B 512
#define NB1    ((NNODES + SCAN_B - 1) / SCAN_B)   // 196

static const int TPB = 256;

// ---------------- device scratch (static, 16B-aligned) ----------------------
__device__ __align__(16) float g_h1  [(size_t)NNODES * F1];
__device__ __align__(16) float g_agg1[(size_t)NNODES * F1];
__device__ __align__(16) float g_h2  [(size_t)NNODES * CO];
__device__ __align__(16) float g_asrc1[NNODES * NH1];
__device__ __align__(16) float g_adst1[NNODES * NH1];
__device__ __align__(16) float g_ex1 [(size_t)ETOT * NH1];
__device__ __align__(16) float g_asrc2[NNODES];
__device__ __align__(16) float g_adst2[NNODES];
__device__ __align__(16) float g_ex2 [ETOT];
// CSR machinery
__device__ int g_esrc[ETOT];
__device__ int g_edst[ETOT];
__device__ int g_csrc[ETOT];
__device__ int g_deg [NNODES];
__device__ int g_scan[NNODES];
__device__ int g_boff[NB1 + 32];
__device__ int g_rowptr[NNODES + 1];
__device__ int g_wcur[NNODES];

// ---------------- helpers ----------------------------------------------------
__device__ __forceinline__ float lrelu(float v) { return v >= 0.f ? v : 0.2f * v; }
__device__ __forceinline__ float4 lrelu4(float4 v) {
    return make_float4(lrelu(v.x), lrelu(v.y), lrelu(v.z), lrelu(v.w));
}
__device__ __forceinline__ float4 max4(float4 a, float4 b) {
    return make_float4(fmaxf(a.x, b.x), fmaxf(a.y, b.y),
                       fmaxf(a.z, b.z), fmaxf(a.w, b.w));
}
__device__ __forceinline__ float4 wred_max4(float4 v) {
#pragma unroll
    for (int o = 16; o > 0; o >>= 1) {
        v.x = fmaxf(v.x, __shfl_xor_sync(0xffffffffu, v.x, o));
        v.y = fmaxf(v.y, __shfl_xor_sync(0xffffffffu, v.y, o));
        v.z = fmaxf(v.z, __shfl_xor_sync(0xffffffffu, v.z, o));
        v.w = fmaxf(v.w, __shfl_xor_sync(0xffffffffu, v.w, o));
    }
    return v;
}
__device__ __forceinline__ float4 wred_sum4(float4 v) {
#pragma unroll
    for (int o = 16; o > 0; o >>= 1) {
        v.x += __shfl_xor_sync(0xffffffffu, v.x, o);
        v.y += __shfl_xor_sync(0xffffffffu, v.y, o);
        v.z += __shfl_xor_sync(0xffffffffu, v.z, o);
        v.w += __shfl_xor_sync(0xffffffffu, v.w, o);
    }
    return v;
}

// ---------------- edge prep: dtype-robust decode + degree histogram ----------
__global__ void k_zero_deg() {
    int i = blockIdx.x * blockDim.x + threadIdx.x;
    if (i < NNODES) g_deg[i] = 0;
}
__global__ void k_prep(const void* __restrict__ ei_raw) {
    int e = blockIdx.x * blockDim.x + threadIdx.x;
    if (e >= ETOT) return;
    int s, d;
    if (e >= E_IN) {
        s = d = e - E_IN;
    } else {
        const long long* e64 = (const long long*)ei_raw;
        bool is64 = true;
#pragma unroll
        for (int q = 0; q < 4; q++) {
            long long v = e64[q];
            if (v < 0 || v >= NNODES) is64 = false;
        }
        if (is64) {
            s = (int)e64[e];
            d = (int)e64[(size_t)E_IN + e];
        } else {
            const int* e32 = (const int*)ei_raw;
            s = e32[e];
            d = e32[E_IN + e];
        }
    }
    g_esrc[e] = s;
    g_edst[e] = d;
    atomicAdd(&g_deg[d], 1);
}

// ---------------- 3-phase exclusive scan over degrees -------------------------
__global__ void __launch_bounds__(SCAN_B) k_scan1() {
    int t = threadIdx.x, b = blockIdx.x;
    int i = b * SCAN_B + t;
    int val = (i < NNODES) ? g_deg[i] : 0;
    int lane = t & 31, wid = t >> 5;
    int v = val;
#pragma unroll
    for (int o = 1; o < 32; o <<= 1) {
        int u = __shfl_up_sync(0xffffffffu, v, o);
        if (lane >= o) v += u;
    }
    __shared__ int wsum[SCAN_B / 32];
    if (lane == 31) wsum[wid] = v;
    __syncthreads();
    if (wid == 0) {
        int w = (lane < SCAN_B / 32) ? wsum[lane] : 0;
#pragma unroll
        for (int o = 1; o < 32; o <<= 1) {
            int u = __shfl_up_sync(0xffffffffu, w, o);
            if (lane >= o) w += u;
        }
        if (lane < SCAN_B / 32) wsum[lane] = w;
    }
    __syncthreads();
    int incl = v + (wid ? wsum[wid - 1] : 0);
    if (i < NNODES) g_scan[i] = incl;
    if (t == SCAN_B - 1) g_boff[b] = incl;   // block total
}
__global__ void k_scan2() {   // 1 block, 256 threads; NB1=196 values
    int t = threadIdx.x;
    int val = (t < NB1) ? g_boff[t] : 0;
    int lane = t & 31, wid = t >> 5;
    int v = val;
#pragma unroll
    for (int o = 1; o < 32; o <<= 1) {
        int u = __shfl_up_sync(0xffffffffu, v, o);
        if (lane >= o) v += u;
    }
    __shared__ int wsum[8];
    if (lane == 31) wsum[wid] = v;
    __syncthreads();
    if (wid == 0) {
        int w = (lane < 8) ? wsum[lane] : 0;
#pragma unroll
        for (int o = 1; o < 8; o <<= 1) {
            int u = __shfl_up_sync(0xffffffffu, w, o);
            if (lane >= o) w += u;
        }
        if (lane < 8) wsum[lane] = w;
    }
    __syncthreads();
    int incl = v + (wid ? wsum[wid - 1] : 0);
    if (t < NB1) g_boff[t] = incl - val;     // exclusive block offset
}
__global__ void k_scan3() {
    int i = blockIdx.x * blockDim.x + threadIdx.x;
    if (i >= NNODES) return;
    int base = g_boff[i / SCAN_B];
    int excl = base + g_scan[i] - g_deg[i];
    g_rowptr[i] = excl;
    g_wcur[i]   = excl;
    if (i == 0) g_rowptr[NNODES] = ETOT;
}
__global__ void k_scatter() {
    int e = blockIdx.x * blockDim.x + threadIdx.x;
    if (e >= ETOT) return;
    int d = g_edst[e];
    int pos = atomicAdd(&g_wcur[d], 1);
    g_csrc[pos] = g_esrc[e];
}

// ---------------- gemm1: C[100000,128] = x[100000,256] @ W1[256,128] ----------
// 128x128 tile, BK=16, 256 threads, 8x8 micro-tile (split 4+4), reg prefetch.
__global__ void __launch_bounds__(256) gemm1_kernel(const float* __restrict__ A,
                                                    const float* __restrict__ B) {
    __shared__ float As[16][128];
    __shared__ float Bs[16][128];
    const int tid = threadIdx.x;
    const int tx = tid & 15, ty = tid >> 4;
    const int row0 = blockIdx.x * 128;

    const int ar = tid & 127;          // A tile row
    const int ac = (tid >> 7) * 8;     // A tile col group (0 or 8)
    const int br = tid >> 4;           // B tile row 0..15
    const int bc = (tid & 15) * 4;     // B tile col 0..60

    float acc[8][8];
#pragma unroll
    for (int i = 0; i < 8; i++)
#pragma unroll
        for (int j = 0; j < 8; j++) acc[i][j] = 0.f;

    float4 pa0 = make_float4(0, 0, 0, 0), pa1 = pa0, pb0, pb1;
    {
        int gr = row0 + ar;
        if (gr < NNODES) {
            pa0 = *(const float4*)&A[(size_t)gr * FIN + ac];
            pa1 = *(const float4*)&A[(size_t)gr * FIN + ac + 4];
        }
        pb0 = *(const float4*)&B[(size_t)br * F1 + bc];
        pb1 = *(const float4*)&B[(size_t)br * F1 + 64 + bc];
    }

    for (int k0 = 0; k0 < FIN; k0 += 16) {
        As[ac + 0][ar] = pa0.x; As[ac + 1][ar] = pa0.y;
        As[ac + 2][ar] = pa0.z; As[ac + 3][ar] = pa0.w;
        As[ac + 4][ar] = pa1.x; As[ac + 5][ar] = pa1.y;
        As[ac + 6][ar] = pa1.z; As[ac + 7][ar] = pa1.w;
        *(float4*)&Bs[br][bc]      = pb0;
        *(float4*)&Bs[br][64 + bc] = pb1;
        __syncthreads();

        int k1 = k0 + 16;
        if (k1 < FIN) {
            int gr = row0 + ar;
            pa0 = pa1 = make_float4(0, 0, 0, 0);
            if (gr < NNODES) {
                pa0 = *(const float4*)&A[(size_t)gr * FIN + k1 + ac];
                pa1 = *(const float4*)&A[(size_t)gr * FIN + k1 + ac + 4];
            }
            pb0 = *(const float4*)&B[(size_t)(k1 + br) * F1 + bc];
            pb1 = *(const float4*)&B[(size_t)(k1 + br) * F1 + 64 + bc];
        }

#pragma unroll
        for (int kk = 0; kk < 16; kk++) {
            float a[8], b[8];
            *(float4*)&a[0] = *(const float4*)&As[kk][ty * 4];
            *(float4*)&a[4] = *(const float4*)&As[kk][64 + ty * 4];
            *(float4*)&b[0] = *(const float4*)&Bs[kk][tx * 4];
            *(float4*)&b[4] = *(const float4*)&Bs[kk][64 + tx * 4];
#pragma unroll
            for (int i = 0; i < 8; i++)
#pragma unroll
                for (int j = 0; j < 8; j++)
                    acc[i][j] = fmaf(a[i], b[j], acc[i][j]);
        }
        __syncthreads();
    }

#pragma unroll
    for (int i = 0; i < 8; i++) {
        int lr = (i < 4) ? (ty * 4 + i) : (64 + ty * 4 + (i - 4));
        int gr = row0 + lr;
        if (gr < NNODES) {
            *(float4*)&g_h1[(size_t)gr * F1 + tx * 4] =
                make_float4(acc[i][0], acc[i][1], acc[i][2], acc[i][3]);
            *(float4*)&g_h1[(size_t)gr * F1 + 64 + tx * 4] =
                make_float4(acc[i][4], acc[i][5], acc[i][6], acc[i][7]);
        }
    }
}

// ---------------- gemm2: g_h2 = g_agg1[100000,128] @ W2[128,64] ---------------
// 64-row tile, BK=16, 256 threads, 4x4 micro-tile.
__global__ void __launch_bounds__(256) gemm2_kernel(const float* __restrict__ B) {
    __shared__ float As[16][64];
    __shared__ float Bs[16][CO];
    const float* A = g_agg1;
    const int tid = threadIdx.x;
    const int tx = tid & 15, ty = tid >> 4;
    const int row0 = blockIdx.x * 64;

    float acc[4][4];
#pragma unroll
    for (int i = 0; i < 4; i++)
#pragma unroll
        for (int j = 0; j < 4; j++) acc[i][j] = 0.f;

    const int a_row = tid >> 2;
    const int a_col = (tid & 3) << 2;

    for (int k0 = 0; k0 < F1; k0 += 16) {
        float4 av = make_float4(0, 0, 0, 0);
        int gr = row0 + a_row;
        if (gr < NNODES) av = *(const float4*)&A[(size_t)gr * F1 + k0 + a_col];
        As[a_col + 0][a_row] = av.x;
        As[a_col + 1][a_row] = av.y;
        As[a_col + 2][a_row] = av.z;
        As[a_col + 3][a_row] = av.w;
        {   // B tile 16x64 = 1024 floats, 256 threads x 1 float4
            int br = tid >> 4, bcc = (tid & 15) * 4;
            *(float4*)&Bs[br][bcc] = *(const float4*)&B[(size_t)(k0 + br) * CO + bcc];
        }
        __syncthreads();
#pragma unroll
        for (int kk = 0; kk < 16; kk++) {
            float4 a4 = *(const float4*)&As[kk][ty * 4];
            float4 b4 = *(const float4*)&Bs[kk][tx * 4];
            float aa[4] = {a4.x, a4.y, a4.z, a4.w};
            float bb[4] = {b4.x, b4.y, b4.z, b4.w};
#pragma unroll
            for (int i = 0; i < 4; i++)
#pragma unroll
                for (int j = 0; j < 4; j++)
                    acc[i][j] = fmaf(aa[i], bb[j], acc[i][j]);
        }
        __syncthreads();
    }
#pragma unroll
    for (int i = 0; i < 4; i++) {
        int gr = row0 + ty * 4 + i;
        if (gr < NNODES)
            *(float4*)&g_h2[(size_t)gr * CO + tx * 4] =
                make_float4(acc[i][0], acc[i][1], acc[i][2], acc[i][3]);
    }
}

// ---------------- attention coefficients --------------------------------------
__global__ void k_att1(const float* __restrict__ att_s,
                       const float* __restrict__ att_d) {
    __shared__ float ss[F1], sd[F1];
    if (threadIdx.x < F1) { ss[threadIdx.x] = att_s[threadIdx.x];
                            sd[threadIdx.x] = att_d[threadIdx.x]; }
    __syncthreads();
    int i = blockIdx.x * blockDim.x + threadIdx.x;
    if (i >= NNODES * NH1) return;
    int n = i >> 2, h = i & 3;
    const float4* hv = (const float4*)&g_h1[(size_t)n * F1 + h * 32];
    const float4* sv = (const float4*)&ss[h * 32];
    const float4* dv = (const float4*)&sd[h * 32];
    float s = 0.f, d = 0.f;
#pragma unroll
    for (int q = 0; q < 8; q++) {
        float4 hh = hv[q], a = sv[q], b = dv[q];
        s += hh.x * a.x + hh.y * a.y + hh.z * a.z + hh.w * a.w;
        d += hh.x * b.x + hh.y * b.y + hh.z * b.z + hh.w * b.w;
    }
    g_asrc1[i] = s;
    g_adst1[i] = d;
}

__global__ void k_att2(const float* __restrict__ att_s,
                       const float* __restrict__ att_d) {
    __shared__ float ss[CO], sd[CO];
    if (threadIdx.x < CO) { ss[threadIdx.x] = att_s[threadIdx.x];
                            sd[threadIdx.x] = att_d[threadIdx.x]; }
    __syncthreads();
    int n = blockIdx.x * blockDim.x + threadIdx.x;
    if (n >= NNODES) return;
    const float4* hv = (const float4*)&g_h2[(size_t)n * CO];
    const float4* sv = (const float4*)ss;
    const float4* dv = (const float4*)sd;
    float s = 0.f, d = 0.f;
#pragma unroll
    for (int q = 0; q < CO / 4; q++) {
        float4 hh = hv[q], a = sv[q], b = dv[q];
        s += hh.x * a.x + hh.y * a.y + hh.z * a.z + hh.w * a.w;
        d += hh.x * b.x + hh.y * b.y + hh.z * b.z + hh.w * b.w;
    }
    g_asrc2[n] = s;
    g_adst2[n] = d;
}

// ---------------- layer-1: fused segment softmax + aggregate (warp/node) -----
__global__ void __launch_bounds__(256) k_l1(const float* __restrict__ b1) {
    int w = (blockIdx.x * blockDim.x + threadIdx.x) >> 5;
    if (w >= NNODES) return;
    const int n = w, lane = threadIdx.x & 31;
    const int beg = g_rowptr[n], end = g_rowptr[n + 1];
    const float4 ad = *(const float4*)&g_adst1[n * 4];

    // pass 1: e = lrelu(a_src[s] + a_dst[n]); running max
    float4 mx = make_float4(-CUDART_INF_F, -CUDART_INF_F, -CUDART_INF_F, -CUDART_INF_F);
    for (int p = beg + lane; p < end; p += 32) {
        int s = g_csrc[p];
        float4 e = lrelu4(make_float4(g_asrc1[s * 4 + 0] + ad.x,
                                      g_asrc1[s * 4 + 1] + ad.y,
                                      g_asrc1[s * 4 + 2] + ad.z,
                                      g_asrc1[s * 4 + 3] + ad.w));
        *(float4*)&g_ex1[(size_t)p * 4] = e;
        mx = max4(mx, e);
    }
    mx = wred_max4(mx);

    // pass 2: exp + sum (rewrite ex in place)
    float4 sm = make_float4(0, 0, 0, 0);
    for (int p = beg + lane; p < end; p += 32) {
        float4 e = *(const float4*)&g_ex1[(size_t)p * 4];
        float4 ex = make_float4(__expf(e.x - mx.x), __expf(e.y - mx.y),
                                __expf(e.z - mx.z), __expf(e.w - mx.w));
        *(float4*)&g_ex1[(size_t)p * 4] = ex;
        sm.x += ex.x; sm.y += ex.y; sm.z += ex.z; sm.w += ex.w;
    }
    sm = wred_sum4(sm);
    float4 inv = make_float4(1.f / (sm.x + EPSV), 1.f / (sm.y + EPSV),
                             1.f / (sm.z + EPSV), 1.f / (sm.w + EPSV));
    __syncwarp();   // cross-lane visibility of g_ex1 rewrites

    // pass 3: aggregate; lane covers features [4*lane, 4*lane+4), head = lane/8
    const int h = lane >> 3;
    const float invh = (h == 0) ? inv.x : (h == 1) ? inv.y : (h == 2) ? inv.z : inv.w;
    float4 acc = make_float4(0, 0, 0, 0);
    for (int p = beg; p < end; ++p) {
        int s = g_csrc[p];                      // warp-uniform broadcast
        float alpha = g_ex1[(size_t)p * 4 + h] * invh;
        float4 hv = *(const float4*)&g_h1[(size_t)s * F1 + lane * 4];
        acc.x = fmaf(hv.x, alpha, acc.x);
        acc.y = fmaf(hv.y, alpha, acc.y);
        acc.z = fmaf(hv.z, alpha, acc.z);
        acc.w = fmaf(hv.w, alpha, acc.w);
    }
    // bias + ELU fused
    float4 b = *(const float4*)&b1[lane * 4];
    float4 v = make_float4(acc.x + b.x, acc.y + b.y, acc.z + b.z, acc.w + b.w);
    v.x = v.x > 0.f ? v.x : expm1f(v.x);
    v.y = v.y > 0.f ? v.y : expm1f(v.y);
    v.z = v.z > 0.f ? v.z : expm1f(v.z);
    v.w = v.w > 0.f ? v.w : expm1f(v.w);
    *(float4*)&g_agg1[(size_t)n * F1 + lane * 4] = v;
}

// ---------------- layer-2: fused segment softmax + aggregate (warp/node) -----
__global__ void __launch_bounds__(256) k_l2(const float* __restrict__ b2,
                                            float* __restrict__ out) {
    int w = (blockIdx.x * blockDim.x + threadIdx.x) >> 5;
    if (w >= NNODES) return;
    const int n = w, lane = threadIdx.x & 31;
    const int beg = g_rowptr[n], end = g_rowptr[n + 1];
    const float adn = g_adst2[n];

    float mx = -CUDART_INF_F;
    for (int p = beg + lane; p < end; p += 32) {
        int s = g_csrc[p];
        float e = lrelu(g_asrc2[s] + adn);
        g_ex2[p] = e;
        mx = fmaxf(mx, e);
    }
#pragma unroll
    for (int o = 16; o > 0; o >>= 1) mx = fmaxf(mx, __shfl_xor_sync(0xffffffffu, mx, o));

    float sm = 0.f;
    for (int p = beg + lane; p < end; p += 32) {
        float ex = __expf(g_ex2[p] - mx);
        g_ex2[p] = ex;
        sm += ex;
    }
#pragma unroll
    for (int o = 16; o > 0; o >>= 1) sm += __shfl_xor_sync(0xffffffffu, sm, o);
    float inv = 1.f / (sm + EPSV);
    __syncwarp();

    float2 acc = make_float2(0, 0);
    for (int p = beg; p < end; ++p) {
        int s = g_csrc[p];
        float alpha = g_ex2[p] * inv;
        float2 hv = *(const float2*)&g_h2[(size_t)s * CO + lane * 2];
        acc.x = fmaf(hv.x, alpha, acc.x);
        acc.y = fmaf(hv.y, alpha, acc.y);
    }
    float2 b = *(const float2*)&b2[lane * 2];
    *(float2*)&out[(size_t)n * CO + lane * 2] = make_float2(acc.x + b.x, acc.y + b.y);
}

// ---------------- launcher -------------------------------------------------------
extern "C" void kernel_launch(void* const* d_in, const int* in_sizes, int n_in,
                              void* d_out, int out_size) {
    const float* x   = (const float*)d_in[0];
    const void*  ei  = d_in[1];
    const float* W1  = (const float*)d_in[2];
    const float* as1 = (const float*)d_in[3];
    const float* ad1 = (const float*)d_in[4];
    const float* b1  = (const float*)d_in[5];
    const float* W2  = (const float*)d_in[6];
    const float* as2 = (const float*)d_in[7];
    const float* ad2 = (const float*)d_in[8];
    const float* b2  = (const float*)d_in[9];
    float* out = (float*)d_out;

    (void)in_sizes; (void)n_in; (void)out_size;

    const int gNode  = (NNODES + TPB - 1) / TPB;
    const int gStats = (NNODES * NH1 + TPB - 1) / TPB;
    const int gEdge  = (ETOT + TPB - 1) / TPB;
    const int gWarp  = (int)(((long long)NNODES * 32 + TPB - 1) / TPB);

    // CSR build
    k_zero_deg<<<gNode, TPB>>>();
    k_prep<<<gEdge, TPB>>>(ei);
    k_scan1<<<NB1, SCAN_B>>>();
    k_scan2<<<1, 256>>>();
    k_scan3<<<gNode, TPB>>>();
    k_scatter<<<gEdge, TPB>>>();

    // layer 1
    gemm1_kernel<<<(NNODES + 127) / 128, 256>>>(x, W1);
    k_att1<<<gStats, TPB>>>(as1, ad1);
    k_l1<<<gWarp, TPB>>>(b1);

    // layer 2
    gemm2_kernel<<<(NNODES + 63) / 64, 256>>>(W2);
    k_att2<<<gNode, TPB>>>(as2, ad2);
    k_l2<<<gWarp, TPB>>>(b2, out);
}

// round 8
// speedup vs baseline: 3.5361x; 1.3053x over previous
#include <cuda_runtime.h>
#include <math_constants.h>

// ---------------------------------------------------------------------------
// GAT 2-layer forward, fixed shapes. CSR-based, zero float atomics.
//   N=100000, Fin=256, L1: H=4 x C=32 (F1=128 concat), L2: 1 x 64.
//   E=1.6M + N self loops.
// R7: gemm1 moved to tensor pipe (mma.sync m16n8k8 tf32, HMMA).
// ---------------------------------------------------------------------------

#define NNODES 100000
#define E_IN   1600000
#define ETOT   (E_IN + NNODES)
#define NH1    4
#define F1     128
#define FIN    256
#define CO     64
#define EPSV   1e-16f
#define SCAN_B 512
#define NB1    ((NNODES + SCAN_B - 1) / SCAN_B)   // 196

static const int TPB = 256;

// ---------------- device scratch (static, 16B-aligned) ----------------------
__device__ __align__(16) float g_h1  [(size_t)NNODES * F1];
__device__ __align__(16) float g_agg1[(size_t)NNODES * F1];
__device__ __align__(16) float g_h2  [(size_t)NNODES * CO];
__device__ __align__(16) float g_asrc1[NNODES * NH1];
__device__ __align__(16) float g_adst1[NNODES * NH1];
__device__ __align__(16) float g_ex1 [(size_t)ETOT * NH1];
__device__ __align__(16) float g_asrc2[NNODES];
__device__ __align__(16) float g_adst2[NNODES];
__device__ __align__(16) float g_ex2 [ETOT];
// CSR machinery
__device__ int g_esrc[ETOT];
__device__ int g_edst[ETOT];
__device__ int g_csrc[ETOT];
__device__ int g_deg [NNODES];
__device__ int g_scan[NNODES];
__device__ int g_boff[NB1 + 32];
__device__ int g_rowptr[NNODES + 1];
__device__ int g_wcur[NNODES];

// ---------------- helpers ----------------------------------------------------
__device__ __forceinline__ float lrelu(float v) { return v >= 0.f ? v : 0.2f * v; }
__device__ __forceinline__ float4 lrelu4(float4 v) {
    return make_float4(lrelu(v.x), lrelu(v.y), lrelu(v.z), lrelu(v.w));
}
__device__ __forceinline__ float4 max4(float4 a, float4 b) {
    return make_float4(fmaxf(a.x, b.x), fmaxf(a.y, b.y),
                       fmaxf(a.z, b.z), fmaxf(a.w, b.w));
}
__device__ __forceinline__ float4 wred_max4(float4 v) {
#pragma unroll
    for (int o = 16; o > 0; o >>= 1) {
        v.x = fmaxf(v.x, __shfl_xor_sync(0xffffffffu, v.x, o));
        v.y = fmaxf(v.y, __shfl_xor_sync(0xffffffffu, v.y, o));
        v.z = fmaxf(v.z, __shfl_xor_sync(0xffffffffu, v.z, o));
        v.w = fmaxf(v.w, __shfl_xor_sync(0xffffffffu, v.w, o));
    }
    return v;
}
__device__ __forceinline__ float4 wred_sum4(float4 v) {
#pragma unroll
    for (int o = 16; o > 0; o >>= 1) {
        v.x += __shfl_xor_sync(0xffffffffu, v.x, o);
        v.y += __shfl_xor_sync(0xffffffffu, v.y, o);
        v.z += __shfl_xor_sync(0xffffffffu, v.z, o);
        v.w += __shfl_xor_sync(0xffffffffu, v.w, o);
    }
    return v;
}
__device__ __forceinline__ unsigned f2tf32(float f) {
    unsigned u;
    asm("cvt.rna.tf32.f32 %0, %1;" : "=r"(u) : "f"(f));
    return u;
}
__device__ __forceinline__ void mma_tf32(float4& d, const unsigned a[4],
                                         unsigned b0, unsigned b1) {
    asm volatile(
        "mma.sync.aligned.m16n8k8.row.col.f32.tf32.tf32.f32 "
        "{%0,%1,%2,%3}, {%4,%5,%6,%7}, {%8,%9}, {%0,%1,%2,%3};\n"
        : "+f"(d.x), "+f"(d.y), "+f"(d.z), "+f"(d.w)
        : "r"(a[0]), "r"(a[1]), "r"(a[2]), "r"(a[3]), "r"(b0), "r"(b1));
}

// ---------------- edge prep: dtype-robust decode + degree histogram ----------
__global__ void k_zero_deg() {
    int i = blockIdx.x * blockDim.x + threadIdx.x;
    if (i < NNODES) g_deg[i] = 0;
}
__global__ void k_prep(const void* __restrict__ ei_raw) {
    int e = blockIdx.x * blockDim.x + threadIdx.x;
    if (e >= ETOT) return;
    int s, d;
    if (e >= E_IN) {
        s = d = e - E_IN;
    } else {
        const long long* e64 = (const long long*)ei_raw;
        bool is64 = true;
#pragma unroll
        for (int q = 0; q < 4; q++) {
            long long v = e64[q];
            if (v < 0 || v >= NNODES) is64 = false;
        }
        if (is64) {
            s = (int)e64[e];
            d = (int)e64[(size_t)E_IN + e];
        } else {
            const int* e32 = (const int*)ei_raw;
            s = e32[e];
            d = e32[E_IN + e];
        }
    }
    g_esrc[e] = s;
    g_edst[e] = d;
    atomicAdd(&g_deg[d], 1);
}

// ---------------- 3-phase exclusive scan over degrees -------------------------
__global__ void __launch_bounds__(SCAN_B) k_scan1() {
    int t = threadIdx.x, b = blockIdx.x;
    int i = b * SCAN_B + t;
    int val = (i < NNODES) ? g_deg[i] : 0;
    int lane = t & 31, wid = t >> 5;
    int v = val;
#pragma unroll
    for (int o = 1; o < 32; o <<= 1) {
        int u = __shfl_up_sync(0xffffffffu, v, o);
        if (lane >= o) v += u;
    }
    __shared__ int wsum[SCAN_B / 32];
    if (lane == 31) wsum[wid] = v;
    __syncthreads();
    if (wid == 0) {
        int w = (lane < SCAN_B / 32) ? wsum[lane] : 0;
#pragma unroll
        for (int o = 1; o < 32; o <<= 1) {
            int u = __shfl_up_sync(0xffffffffu, w, o);
            if (lane >= o) w += u;
        }
        if (lane < SCAN_B / 32) wsum[lane] = w;
    }
    __syncthreads();
    int incl = v + (wid ? wsum[wid - 1] : 0);
    if (i < NNODES) g_scan[i] = incl;
    if (t == SCAN_B - 1) g_boff[b] = incl;
}
__global__ void k_scan2() {
    int t = threadIdx.x;
    int val = (t < NB1) ? g_boff[t] : 0;
    int lane = t & 31, wid = t >> 5;
    int v = val;
#pragma unroll
    for (int o = 1; o < 32; o <<= 1) {
        int u = __shfl_up_sync(0xffffffffu, v, o);
        if (lane >= o) v += u;
    }
    __shared__ int wsum[8];
    if (lane == 31) wsum[wid] = v;
    __syncthreads();
    if (wid == 0) {
        int w = (lane < 8) ? wsum[lane] : 0;
#pragma unroll
        for (int o = 1; o < 8; o <<= 1) {
            int u = __shfl_up_sync(0xffffffffu, w, o);
            if (lane >= o) w += u;
        }
        if (lane < 8) wsum[lane] = w;
    }
    __syncthreads();
    int incl = v + (wid ? wsum[wid - 1] : 0);
    if (t < NB1) g_boff[t] = incl - val;
}
__global__ void k_scan3() {
    int i = blockIdx.x * blockDim.x + threadIdx.x;
    if (i >= NNODES) return;
    int base = g_boff[i / SCAN_B];
    int excl = base + g_scan[i] - g_deg[i];
    g_rowptr[i] = excl;
    g_wcur[i]   = excl;
    if (i == 0) g_rowptr[NNODES] = ETOT;
}
__global__ void k_scatter() {
    int e = blockIdx.x * blockDim.x + threadIdx.x;
    if (e >= ETOT) return;
    int d = g_edst[e];
    int pos = atomicAdd(&g_wcur[d], 1);
    g_csrc[pos] = g_esrc[e];
}

// ---------------- gemm1: g_h1 = x[100000,256] @ W1[256,128], tf32 HMMA --------
// 128x128 tile, BK=32, 8 warps (4x2), warp tile 32x64 = 2x8 m16n8k8 frags.
__global__ void __launch_bounds__(256) gemm1_kernel(const float* __restrict__ A,
                                                    const float* __restrict__ B) {
    __shared__ unsigned As[128][36];   // pad 36: frag loads conflict-free
    __shared__ unsigned Bs[32][136];   // pad 136: frag loads conflict-free
    const int tid  = threadIdx.x;
    const int lane = tid & 31, wid = tid >> 5;
    const int wm = (wid & 3) * 32;     // warp row offset within tile
    const int wn = (wid >> 2) * 64;    // warp col offset
    const int row0 = blockIdx.x * 128;
    const int g = lane >> 2, tg = lane & 3;

    float4 acc[2][8];
#pragma unroll
    for (int mt = 0; mt < 2; mt++)
#pragma unroll
        for (int nt = 0; nt < 8; nt++) acc[mt][nt] = make_float4(0, 0, 0, 0);

    for (int k0 = 0; k0 < FIN; k0 += 32) {
        // stage A tile (128x32) as tf32
#pragma unroll
        for (int q = 0; q < 4; q++) {
            int f4 = tid + q * 256;
            int r = f4 >> 3, c = (f4 & 7) * 4;
            float4 v = make_float4(0, 0, 0, 0);
            int gr = row0 + r;
            if (gr < NNODES) v = *(const float4*)&A[(size_t)gr * FIN + k0 + c];
            *(uint4*)&As[r][c] =
                make_uint4(f2tf32(v.x), f2tf32(v.y), f2tf32(v.z), f2tf32(v.w));
        }
        // stage B tile (32x128) as tf32
#pragma unroll
        for (int q = 0; q < 4; q++) {
            int f4 = tid + q * 256;
            int r = f4 >> 5, c = (f4 & 31) * 4;
            float4 v = *(const float4*)&B[(size_t)(k0 + r) * F1 + c];
            *(uint4*)&Bs[r][c] =
                make_uint4(f2tf32(v.x), f2tf32(v.y), f2tf32(v.z), f2tf32(v.w));
        }
        __syncthreads();

#pragma unroll
        for (int kk = 0; kk < 32; kk += 8) {
            unsigned a[2][4];
#pragma unroll
            for (int mt = 0; mt < 2; mt++) {
                int rb = wm + mt * 16;
                a[mt][0] = As[rb + g][kk + tg];
                a[mt][1] = As[rb + 8 + g][kk + tg];
                a[mt][2] = As[rb + g][kk + tg + 4];
                a[mt][3] = As[rb + 8 + g][kk + tg + 4];
            }
#pragma unroll
            for (int nt = 0; nt < 8; nt++) {
                unsigned b0 = Bs[kk + tg][wn + nt * 8 + g];
                unsigned b1 = Bs[kk + 4 + tg][wn + nt * 8 + g];
                mma_tf32(acc[0][nt], a[0], b0, b1);
                mma_tf32(acc[1][nt], a[1], b0, b1);
            }
        }
        __syncthreads();
    }

#pragma unroll
    for (int mt = 0; mt < 2; mt++) {
#pragma unroll
        for (int nt = 0; nt < 8; nt++) {
            int r = row0 + wm + mt * 16 + g;
            int c = wn + nt * 8 + tg * 2;
            if (r < NNODES)
                *(float2*)&g_h1[(size_t)r * F1 + c] =
                    make_float2(acc[mt][nt].x, acc[mt][nt].y);
            if (r + 8 < NNODES)
                *(float2*)&g_h1[(size_t)(r + 8) * F1 + c] =
                    make_float2(acc[mt][nt].z, acc[mt][nt].w);
        }
    }
}

// ---------------- gemm2: g_h2 = g_agg1[100000,128] @ W2[128,64] (fp32 SIMT) ---
__global__ void __launch_bounds__(256) gemm2_kernel(const float* __restrict__ B) {
    __shared__ float As[16][64];
    __shared__ float Bs[16][CO];
    const float* A = g_agg1;
    const int tid = threadIdx.x;
    const int tx = tid & 15, ty = tid >> 4;
    const int row0 = blockIdx.x * 64;

    float acc[4][4];
#pragma unroll
    for (int i = 0; i < 4; i++)
#pragma unroll
        for (int j = 0; j < 4; j++) acc[i][j] = 0.f;

    const int a_row = tid >> 2;
    const int a_col = (tid & 3) << 2;

    for (int k0 = 0; k0 < F1; k0 += 16) {
        float4 av = make_float4(0, 0, 0, 0);
        int gr = row0 + a_row;
        if (gr < NNODES) av = *(const float4*)&A[(size_t)gr * F1 + k0 + a_col];
        As[a_col + 0][a_row] = av.x;
        As[a_col + 1][a_row] = av.y;
        As[a_col + 2][a_row] = av.z;
        As[a_col + 3][a_row] = av.w;
        {
            int br = tid >> 4, bcc = (tid & 15) * 4;
            *(float4*)&Bs[br][bcc] = *(const float4*)&B[(size_t)(k0 + br) * CO + bcc];
        }
        __syncthreads();
#pragma unroll
        for (int kk = 0; kk < 16; kk++) {
            float4 a4 = *(const float4*)&As[kk][ty * 4];
            float4 b4 = *(const float4*)&Bs[kk][tx * 4];
            float aa[4] = {a4.x, a4.y, a4.z, a4.w};
            float bb[4] = {b4.x, b4.y, b4.z, b4.w};
#pragma unroll
            for (int i = 0; i < 4; i++)
#pragma unroll
                for (int j = 0; j < 4; j++)
                    acc[i][j] = fmaf(aa[i], bb[j], acc[i][j]);
        }
        __syncthreads();
    }
#pragma unroll
    for (int i = 0; i < 4; i++) {
        int gr = row0 + ty * 4 + i;
        if (gr < NNODES)
            *(float4*)&g_h2[(size_t)gr * CO + tx * 4] =
                make_float4(acc[i][0], acc[i][1], acc[i][2], acc[i][3]);
    }
}

// ---------------- attention coefficients --------------------------------------
__global__ void k_att1(const float* __restrict__ att_s,
                       const float* __restrict__ att_d) {
    __shared__ float ss[F1], sd[F1];
    if (threadIdx.x < F1) { ss[threadIdx.x] = att_s[threadIdx.x];
                            sd[threadIdx.x] = att_d[threadIdx.x]; }
    __syncthreads();
    int i = blockIdx.x * blockDim.x + threadIdx.x;
    if (i >= NNODES * NH1) return;
    int n = i >> 2, h = i & 3;
    const float4* hv = (const float4*)&g_h1[(size_t)n * F1 + h * 32];
    const float4* sv = (const float4*)&ss[h * 32];
    const float4* dv = (const float4*)&sd[h * 32];
    float s = 0.f, d = 0.f;
#pragma unroll
    for (int q = 0; q < 8; q++) {
        float4 hh = hv[q], a = sv[q], b = dv[q];
        s += hh.x * a.x + hh.y * a.y + hh.z * a.z + hh.w * a.w;
        d += hh.x * b.x + hh.y * b.y + hh.z * b.z + hh.w * b.w;
    }
    g_asrc1[i] = s;
    g_adst1[i] = d;
}

__global__ void k_att2(const float* __restrict__ att_s,
                       const float* __restrict__ att_d) {
    __shared__ float ss[CO], sd[CO];
    if (threadIdx.x < CO) { ss[threadIdx.x] = att_s[threadIdx.x];
                            sd[threadIdx.x] = att_d[threadIdx.x]; }
    __syncthreads();
    int n = blockIdx.x * blockDim.x + threadIdx.x;
    if (n >= NNODES) return;
    const float4* hv = (const float4*)&g_h2[(size_t)n * CO];
    const float4* sv = (const float4*)ss;
    const float4* dv = (const float4*)sd;
    float s = 0.f, d = 0.f;
#pragma unroll
    for (int q = 0; q < CO / 4; q++) {
        float4 hh = hv[q], a = sv[q], b = dv[q];
        s += hh.x * a.x + hh.y * a.y + hh.z * a.z + hh.w * a.w;
        d += hh.x * b.x + hh.y * b.y + hh.z * b.z + hh.w * b.w;
    }
    g_asrc2[n] = s;
    g_adst2[n] = d;
}

// ---------------- layer-1: fused segment softmax + aggregate (warp/node) -----
__global__ void __launch_bounds__(256) k_l1(const float* __restrict__ b1) {
    int w = (blockIdx.x * blockDim.x + threadIdx.x) >> 5;
    if (w >= NNODES) return;
    const int n = w, lane = threadIdx.x & 31;
    const int beg = g_rowptr[n], end = g_rowptr[n + 1];
    const float4 ad = *(const float4*)&g_adst1[n * 4];

    float4 mx = make_float4(-CUDART_INF_F, -CUDART_INF_F, -CUDART_INF_F, -CUDART_INF_F);
    for (int p = beg + lane; p < end; p += 32) {
        int s = g_csrc[p];
        float4 e = lrelu4(make_float4(g_asrc1[s * 4 + 0] + ad.x,
                                      g_asrc1[s * 4 + 1] + ad.y,
                                      g_asrc1[s * 4 + 2] + ad.z,
                                      g_asrc1[s * 4 + 3] + ad.w));
        *(float4*)&g_ex1[(size_t)p * 4] = e;
        mx = max4(mx, e);
    }
    mx = wred_max4(mx);

    float4 sm = make_float4(0, 0, 0, 0);
    for (int p = beg + lane; p < end; p += 32) {
        float4 e = *(const float4*)&g_ex1[(size_t)p * 4];
        float4 ex = make_float4(__expf(e.x - mx.x), __expf(e.y - mx.y),
                                __expf(e.z - mx.z), __expf(e.w - mx.w));
        *(float4*)&g_ex1[(size_t)p * 4] = ex;
        sm.x += ex.x; sm.y += ex.y; sm.z += ex.z; sm.w += ex.w;
    }
    sm = wred_sum4(sm);
    float4 inv = make_float4(1.f / (sm.x + EPSV), 1.f / (sm.y + EPSV),
                             1.f / (sm.z + EPSV), 1.f / (sm.w + EPSV));
    __syncwarp();

    const int h = lane >> 3;
    const float invh = (h == 0) ? inv.x : (h == 1) ? inv.y : (h == 2) ? inv.z : inv.w;
    float4 acc = make_float4(0, 0, 0, 0);
    for (int p = beg; p < end; ++p) {
        int s = g_csrc[p];
        float alpha = g_ex1[(size_t)p * 4 + h] * invh;
        float4 hv = *(const float4*)&g_h1[(size_t)s * F1 + lane * 4];
        acc.x = fmaf(hv.x, alpha, acc.x);
        acc.y = fmaf(hv.y, alpha, acc.y);
        acc.z = fmaf(hv.z, alpha, acc.z);
        acc.w = fmaf(hv.w, alpha, acc.w);
    }
    float4 b = *(const float4*)&b1[lane * 4];
    float4 v = make_float4(acc.x + b.x, acc.y + b.y, acc.z + b.z, acc.w + b.w);
    v.x = v.x > 0.f ? v.x : expm1f(v.x);
    v.y = v.y > 0.f ? v.y : expm1f(v.y);
    v.z = v.z > 0.f ? v.z : expm1f(v.z);
    v.w = v.w > 0.f ? v.w : expm1f(v.w);
    *(float4*)&g_agg1[(size_t)n * F1 + lane * 4] = v;
}

// ---------------- layer-2: fused segment softmax + aggregate (warp/node) -----
__global__ void __launch_bounds__(256) k_l2(const float* __restrict__ b2,
                                            float* __restrict__ out) {
    int w = (blockIdx.x * blockDim.x + threadIdx.x) >> 5;
    if (w >= NNODES) return;
    const int n = w, lane = threadIdx.x & 31;
    const int beg = g_rowptr[n], end = g_rowptr[n + 1];
    const float adn = g_adst2[n];

    float mx = -CUDART_INF_F;
    for (int p = beg + lane; p < end; p += 32) {
        int s = g_csrc[p];
        float e = lrelu(g_asrc2[s] + adn);
        g_ex2[p] = e;
        mx = fmaxf(mx, e);
    }
#pragma unroll
    for (int o = 16; o > 0; o >>= 1) mx = fmaxf(mx, __shfl_xor_sync(0xffffffffu, mx, o));

    float sm = 0.f;
    for (int p = beg + lane; p < end; p += 32) {
        float ex = __expf(g_ex2[p] - mx);
        g_ex2[p] = ex;
        sm += ex;
    }
#pragma unroll
    for (int o = 16; o > 0; o >>= 1) sm += __shfl_xor_sync(0xffffffffu, sm, o);
    float inv = 1.f / (sm + EPSV);
    __syncwarp();

    float2 acc = make_float2(0, 0);
    for (int p = beg; p < end; ++p) {
        int s = g_csrc[p];
        float alpha = g_ex2[p] * inv;
        float2 hv = *(const float2*)&g_h2[(size_t)s * CO + lane * 2];
        acc.x = fmaf(hv.x, alpha, acc.x);
        acc.y = fmaf(hv.y, alpha, acc.y);
    }
    float2 b = *(const float2*)&b2[lane * 2];
    *(float2*)&out[(size_t)n * CO + lane * 2] = make_float2(acc.x + b.x, acc.y + b.y);
}

// ---------------- launcher -------------------------------------------------------
extern "C" void kernel_launch(void* const* d_in, const int* in_sizes, int n_in,
                              void* d_out, int out_size) {
    const float* x   = (const float*)d_in[0];
    const void*  ei  = d_in[1];
    const float* W1  = (const float*)d_in[2];
    const float* as1 = (const float*)d_in[3];
    const float* ad1 = (const float*)d_in[4];
    const float* b1  = (const float*)d_in[5];
    const float* W2  = (const float*)d_in[6];
    const float* as2 = (const float*)d_in[7];
    const float* ad2 = (const float*)d_in[8];
    const float* b2  = (const float*)d_in[9];
    float* out = (float*)d_out;

    (void)in_sizes; (void)n_in; (void)out_size;

    const int gNode  = (NNODES + TPB - 1) / TPB;
    const int gStats = (NNODES * NH1 + TPB - 1) / TPB;
    const int gEdge  = (ETOT + TPB - 1) / TPB;
    const int gWarp  = (int)(((long long)NNODES * 32 + TPB - 1) / TPB);

    // CSR build
    k_zero_deg<<<gNode, TPB>>>();
    k_prep<<<gEdge, TPB>>>(ei);
    k_scan1<<<NB1, SCAN_B>>>();
    k_scan2<<<1, 256>>>();
    k_scan3<<<gNode, TPB>>>();
    k_scatter<<<gEdge, TPB>>>();

    // layer 1
    gemm1_kernel<<<(NNODES + 127) / 128, 256>>>(x, W1);
    k_att1<<<gStats, TPB>>>(as1, ad1);
    k_l1<<<gWarp, TPB>>>(b1);

    // layer 2
    gemm2_kernel<<<(NNODES + 63) / 64, 256>>>(W2);
    k_att2<<<gNode, TPB>>>(as2, ad2);
    k_l2<<<gWarp, TPB>>>(b2, out);
}

// round 9
// speedup vs baseline: 3.8242x; 1.0815x over previous
#include <cuda_runtime.h>
#include <math_constants.h>

// ---------------------------------------------------------------------------
// GAT 2-layer forward, fixed shapes. CSR-based, zero float atomics.
//   N=100000, Fin=256, L1: H=4 x C=32 (F1=128 concat), L2: 1 x 64.
//   E=1.6M + N self loops.
// R9: gemm2 on tensor pipe (tf32 HMMA); k_l1/k_l2 softmax register-resident
//     (smem alpha broadcast, shuffle src ids), global ex arrays only as
//     deg>64 fallback.
// ---------------------------------------------------------------------------

#define NNODES 100000
#define E_IN   1600000
#define ETOT   (E_IN + NNODES)
#define NH1    4
#define F1     128
#define FIN    256
#define CO     64
#define EPSV   1e-16f
#define SCAN_B 512
#define NB1    ((NNODES + SCAN_B - 1) / SCAN_B)   // 196

static const int TPB = 256;

// ---------------- device scratch (static, 16B-aligned) ----------------------
__device__ __align__(16) float g_h1  [(size_t)NNODES * F1];
__device__ __align__(16) float g_agg1[(size_t)NNODES * F1];
__device__ __align__(16) float g_h2  [(size_t)NNODES * CO];
__device__ __align__(16) float g_asrc1[NNODES * NH1];
__device__ __align__(16) float g_adst1[NNODES * NH1];
__device__ __align__(16) float g_ex1 [(size_t)ETOT * NH1];   // deg>64 fallback only
__device__ __align__(16) float g_asrc2[NNODES];
__device__ __align__(16) float g_adst2[NNODES];
__device__ __align__(16) float g_ex2 [ETOT];                 // deg>64 fallback only
// CSR machinery
__device__ int g_esrc[ETOT];
__device__ int g_edst[ETOT];
__device__ int g_csrc[ETOT];
__device__ int g_deg [NNODES];
__device__ int g_scan[NNODES];
__device__ int g_boff[NB1 + 32];
__device__ int g_rowptr[NNODES + 1];
__device__ int g_wcur[NNODES];

// ---------------- helpers ----------------------------------------------------
__device__ __forceinline__ float lrelu(float v) { return v >= 0.f ? v : 0.2f * v; }
__device__ __forceinline__ float4 lrelu4(float4 v) {
    return make_float4(lrelu(v.x), lrelu(v.y), lrelu(v.z), lrelu(v.w));
}
__device__ __forceinline__ float4 max4(float4 a, float4 b) {
    return make_float4(fmaxf(a.x, b.x), fmaxf(a.y, b.y),
                       fmaxf(a.z, b.z), fmaxf(a.w, b.w));
}
__device__ __forceinline__ float4 exp4(float4 a, float4 m) {
    return make_float4(__expf(a.x - m.x), __expf(a.y - m.y),
                       __expf(a.z - m.z), __expf(a.w - m.w));
}
__device__ __forceinline__ float4 wred_max4(float4 v) {
#pragma unroll
    for (int o = 16; o > 0; o >>= 1) {
        v.x = fmaxf(v.x, __shfl_xor_sync(0xffffffffu, v.x, o));
        v.y = fmaxf(v.y, __shfl_xor_sync(0xffffffffu, v.y, o));
        v.z = fmaxf(v.z, __shfl_xor_sync(0xffffffffu, v.z, o));
        v.w = fmaxf(v.w, __shfl_xor_sync(0xffffffffu, v.w, o));
    }
    return v;
}
__device__ __forceinline__ float4 wred_sum4(float4 v) {
#pragma unroll
    for (int o = 16; o > 0; o >>= 1) {
        v.x += __shfl_xor_sync(0xffffffffu, v.x, o);
        v.y += __shfl_xor_sync(0xffffffffu, v.y, o);
        v.z += __shfl_xor_sync(0xffffffffu, v.z, o);
        v.w += __shfl_xor_sync(0xffffffffu, v.w, o);
    }
    return v;
}
__device__ __forceinline__ unsigned f2tf32(float f) {
    unsigned u;
    asm("cvt.rna.tf32.f32 %0, %1;" : "=r"(u) : "f"(f));
    return u;
}
__device__ __forceinline__ void mma_tf32(float4& d, const unsigned a[4],
                                         unsigned b0, unsigned b1) {
    asm volatile(
        "mma.sync.aligned.m16n8k8.row.col.f32.tf32.tf32.f32 "
        "{%0,%1,%2,%3}, {%4,%5,%6,%7}, {%8,%9}, {%0,%1,%2,%3};\n"
        : "+f"(d.x), "+f"(d.y), "+f"(d.z), "+f"(d.w)
        : "r"(a[0]), "r"(a[1]), "r"(a[2]), "r"(a[3]), "r"(b0), "r"(b1));
}

// ---------------- edge prep: dtype-robust decode + degree histogram ----------
__global__ void k_zero_deg() {
    int i = blockIdx.x * blockDim.x + threadIdx.x;
    if (i < NNODES) g_deg[i] = 0;
}
__global__ void k_prep(const void* __restrict__ ei_raw) {
    int e = blockIdx.x * blockDim.x + threadIdx.x;
    if (e >= ETOT) return;
    int s, d;
    if (e >= E_IN) {
        s = d = e - E_IN;
    } else {
        const long long* e64 = (const long long*)ei_raw;
        bool is64 = true;
#pragma unroll
        for (int q = 0; q < 4; q++) {
            long long v = e64[q];
            if (v < 0 || v >= NNODES) is64 = false;
        }
        if (is64) {
            s = (int)e64[e];
            d = (int)e64[(size_t)E_IN + e];
        } else {
            const int* e32 = (const int*)ei_raw;
            s = e32[e];
            d = e32[E_IN + e];
        }
    }
    g_esrc[e] = s;
    g_edst[e] = d;
    atomicAdd(&g_deg[d], 1);
}

// ---------------- 3-phase exclusive scan over degrees -------------------------
__global__ void __launch_bounds__(SCAN_B) k_scan1() {
    int t = threadIdx.x, b = blockIdx.x;
    int i = b * SCAN_B + t;
    int val = (i < NNODES) ? g_deg[i] : 0;
    int lane = t & 31, wid = t >> 5;
    int v = val;
#pragma unroll
    for (int o = 1; o < 32; o <<= 1) {
        int u = __shfl_up_sync(0xffffffffu, v, o);
        if (lane >= o) v += u;
    }
    __shared__ int wsum[SCAN_B / 32];
    if (lane == 31) wsum[wid] = v;
    __syncthreads();
    if (wid == 0) {
        int w = (lane < SCAN_B / 32) ? wsum[lane] : 0;
#pragma unroll
        for (int o = 1; o < 32; o <<= 1) {
            int u = __shfl_up_sync(0xffffffffu, w, o);
            if (lane >= o) w += u;
        }
        if (lane < SCAN_B / 32) wsum[lane] = w;
    }
    __syncthreads();
    int incl = v + (wid ? wsum[wid - 1] : 0);
    if (i < NNODES) g_scan[i] = incl;
    if (t == SCAN_B - 1) g_boff[b] = incl;
}
__global__ void k_scan2() {
    int t = threadIdx.x;
    int val = (t < NB1) ? g_boff[t] : 0;
    int lane = t & 31, wid = t >> 5;
    int v = val;
#pragma unroll
    for (int o = 1; o < 32; o <<= 1) {
        int u = __shfl_up_sync(0xffffffffu, v, o);
        if (lane >= o) v += u;
    }
    __shared__ int wsum[8];
    if (lane == 31) wsum[wid] = v;
    __syncthreads();
    if (wid == 0) {
        int w = (lane < 8) ? wsum[lane] : 0;
#pragma unroll
        for (int o = 1; o < 8; o <<= 1) {
            int u = __shfl_up_sync(0xffffffffu, w, o);
            if (lane >= o) w += u;
        }
        if (lane < 8) wsum[lane] = w;
    }
    __syncthreads();
    int incl = v + (wid ? wsum[wid - 1] : 0);
    if (t < NB1) g_boff[t] = incl - val;
}
__global__ void k_scan3() {
    int i = blockIdx.x * blockDim.x + threadIdx.x;
    if (i >= NNODES) return;
    int base = g_boff[i / SCAN_B];
    int excl = base + g_scan[i] - g_deg[i];
    g_rowptr[i] = excl;
    g_wcur[i]   = excl;
    if (i == 0) g_rowptr[NNODES] = ETOT;
}
__global__ void k_scatter() {
    int e = blockIdx.x * blockDim.x + threadIdx.x;
    if (e >= ETOT) return;
    int d = g_edst[e];
    int pos = atomicAdd(&g_wcur[d], 1);
    g_csrc[pos] = g_esrc[e];
}

// ---------------- gemm1: g_h1 = x[100000,256] @ W1[256,128], tf32 HMMA --------
__global__ void __launch_bounds__(256) gemm1_kernel(const float* __restrict__ A,
                                                    const float* __restrict__ B) {
    __shared__ unsigned As[128][36];
    __shared__ unsigned Bs[32][136];
    const int tid  = threadIdx.x;
    const int lane = tid & 31, wid = tid >> 5;
    const int wm = (wid & 3) * 32;
    const int wn = (wid >> 2) * 64;
    const int row0 = blockIdx.x * 128;
    const int g = lane >> 2, tg = lane & 3;

    float4 acc[2][8];
#pragma unroll
    for (int mt = 0; mt < 2; mt++)
#pragma unroll
        for (int nt = 0; nt < 8; nt++) acc[mt][nt] = make_float4(0, 0, 0, 0);

    for (int k0 = 0; k0 < FIN; k0 += 32) {
#pragma unroll
        for (int q = 0; q < 4; q++) {
            int f4 = tid + q * 256;
            int r = f4 >> 3, c = (f4 & 7) * 4;
            float4 v = make_float4(0, 0, 0, 0);
            int gr = row0 + r;
            if (gr < NNODES) v = *(const float4*)&A[(size_t)gr * FIN + k0 + c];
            *(uint4*)&As[r][c] =
                make_uint4(f2tf32(v.x), f2tf32(v.y), f2tf32(v.z), f2tf32(v.w));
        }
#pragma unroll
        for (int q = 0; q < 4; q++) {
            int f4 = tid + q * 256;
            int r = f4 >> 5, c = (f4 & 31) * 4;
            float4 v = *(const float4*)&B[(size_t)(k0 + r) * F1 + c];
            *(uint4*)&Bs[r][c] =
                make_uint4(f2tf32(v.x), f2tf32(v.y), f2tf32(v.z), f2tf32(v.w));
        }
        __syncthreads();

#pragma unroll
        for (int kk = 0; kk < 32; kk += 8) {
            unsigned a[2][4];
#pragma unroll
            for (int mt = 0; mt < 2; mt++) {
                int rb = wm + mt * 16;
                a[mt][0] = As[rb + g][kk + tg];
                a[mt][1] = As[rb + 8 + g][kk + tg];
                a[mt][2] = As[rb + g][kk + tg + 4];
                a[mt][3] = As[rb + 8 + g][kk + tg + 4];
            }
#pragma unroll
            for (int nt = 0; nt < 8; nt++) {
                unsigned b0 = Bs[kk + tg][wn + nt * 8 + g];
                unsigned b1 = Bs[kk + 4 + tg][wn + nt * 8 + g];
                mma_tf32(acc[0][nt], a[0], b0, b1);
                mma_tf32(acc[1][nt], a[1], b0, b1);
            }
        }
        __syncthreads();
    }

#pragma unroll
    for (int mt = 0; mt < 2; mt++) {
#pragma unroll
        for (int nt = 0; nt < 8; nt++) {
            int r = row0 + wm + mt * 16 + g;
            int c = wn + nt * 8 + tg * 2;
            if (r < NNODES)
                *(float2*)&g_h1[(size_t)r * F1 + c] =
                    make_float2(acc[mt][nt].x, acc[mt][nt].y);
            if (r + 8 < NNODES)
                *(float2*)&g_h1[(size_t)(r + 8) * F1 + c] =
                    make_float2(acc[mt][nt].z, acc[mt][nt].w);
        }
    }
}

// ---------------- gemm2: g_h2 = g_agg1[100000,128] @ W2[128,64], tf32 HMMA ----
// 128x64 tile, BK=32, 8 warps (4 along M x 2 along N), warp tile 32x32.
__global__ void __launch_bounds__(256) gemm2_kernel(const float* __restrict__ B) {
    __shared__ unsigned As[128][36];
    __shared__ unsigned Bs[32][72];
    const float* A = g_agg1;
    const int tid  = threadIdx.x;
    const int lane = tid & 31, wid = tid >> 5;
    const int wm = (wid & 3) * 32;
    const int wn = (wid >> 2) * 32;
    const int row0 = blockIdx.x * 128;
    const int g = lane >> 2, tg = lane & 3;

    float4 acc[2][4];
#pragma unroll
    for (int mt = 0; mt < 2; mt++)
#pragma unroll
        for (int nt = 0; nt < 4; nt++) acc[mt][nt] = make_float4(0, 0, 0, 0);

    for (int k0 = 0; k0 < F1; k0 += 32) {
#pragma unroll
        for (int q = 0; q < 4; q++) {
            int f4 = tid + q * 256;
            int r = f4 >> 3, c = (f4 & 7) * 4;
            float4 v = make_float4(0, 0, 0, 0);
            int gr = row0 + r;
            if (gr < NNODES) v = *(const float4*)&A[(size_t)gr * F1 + k0 + c];
            *(uint4*)&As[r][c] =
                make_uint4(f2tf32(v.x), f2tf32(v.y), f2tf32(v.z), f2tf32(v.w));
        }
#pragma unroll
        for (int q = 0; q < 2; q++) {
            int f4 = tid + q * 256;
            int r = f4 >> 4, c = (f4 & 15) * 4;
            float4 v = *(const float4*)&B[(size_t)(k0 + r) * CO + c];
            *(uint4*)&Bs[r][c] =
                make_uint4(f2tf32(v.x), f2tf32(v.y), f2tf32(v.z), f2tf32(v.w));
        }
        __syncthreads();

#pragma unroll
        for (int kk = 0; kk < 32; kk += 8) {
            unsigned a[2][4];
#pragma unroll
            for (int mt = 0; mt < 2; mt++) {
                int rb = wm + mt * 16;
                a[mt][0] = As[rb + g][kk + tg];
                a[mt][1] = As[rb + 8 + g][kk + tg];
                a[mt][2] = As[rb + g][kk + tg + 4];
                a[mt][3] = As[rb + 8 + g][kk + tg + 4];
            }
#pragma unroll
            for (int nt = 0; nt < 4; nt++) {
                unsigned b0 = Bs[kk + tg][wn + nt * 8 + g];
                unsigned b1 = Bs[kk + 4 + tg][wn + nt * 8 + g];
                mma_tf32(acc[0][nt], a[0], b0, b1);
                mma_tf32(acc[1][nt], a[1], b0, b1);
            }
        }
        __syncthreads();
    }

#pragma unroll
    for (int mt = 0; mt < 2; mt++) {
#pragma unroll
        for (int nt = 0; nt < 4; nt++) {
            int r = row0 + wm + mt * 16 + g;
            int c = wn + nt * 8 + tg * 2;
            if (r < NNODES)
                *(float2*)&g_h2[(size_t)r * CO + c] =
                    make_float2(acc[mt][nt].x, acc[mt][nt].y);
            if (r + 8 < NNODES)
                *(float2*)&g_h2[(size_t)(r + 8) * CO + c] =
                    make_float2(acc[mt][nt].z, acc[mt][nt].w);
        }
    }
}

// ---------------- attention coefficients --------------------------------------
__global__ void k_att1(const float* __restrict__ att_s,
                       const float* __restrict__ att_d) {
    __shared__ float ss[F1], sd[F1];
    if (threadIdx.x < F1) { ss[threadIdx.x] = att_s[threadIdx.x];
                            sd[threadIdx.x] = att_d[threadIdx.x]; }
    __syncthreads();
    int i = blockIdx.x * blockDim.x + threadIdx.x;
    if (i >= NNODES * NH1) return;
    int n = i >> 2, h = i & 3;
    const float4* hv = (const float4*)&g_h1[(size_t)n * F1 + h * 32];
    const float4* sv = (const float4*)&ss[h * 32];
    const float4* dv = (const float4*)&sd[h * 32];
    float s = 0.f, d = 0.f;
#pragma unroll
    for (int q = 0; q < 8; q++) {
        float4 hh = hv[q], a = sv[q], b = dv[q];
        s += hh.x * a.x + hh.y * a.y + hh.z * a.z + hh.w * a.w;
        d += hh.x * b.x + hh.y * b.y + hh.z * b.z + hh.w * b.w;
    }
    g_asrc1[i] = s;
    g_adst1[i] = d;
}

__global__ void k_att2(const float* __restrict__ att_s,
                       const float* __restrict__ att_d) {
    __shared__ float ss[CO], sd[CO];
    if (threadIdx.x < CO) { ss[threadIdx.x] = att_s[threadIdx.x];
                            sd[threadIdx.x] = att_d[threadIdx.x]; }
    __syncthreads();
    int n = blockIdx.x * blockDim.x + threadIdx.x;
    if (n >= NNODES) return;
    const float4* hv = (const float4*)&g_h2[(size_t)n * CO];
    const float4* sv = (const float4*)ss;
    const float4* dv = (const float4*)sd;
    float s = 0.f, d = 0.f;
#pragma unroll
    for (int q = 0; q < CO / 4; q++) {
        float4 hh = hv[q], a = sv[q], b = dv[q];
        s += hh.x * a.x + hh.y * a.y + hh.z * a.z + hh.w * a.w;
        d += hh.x * b.x + hh.y * b.y + hh.z * b.z + hh.w * b.w;
    }
    g_asrc2[n] = s;
    g_adst2[n] = d;
}

// ---------------- layer-1: fused softmax+aggregate, register-resident ---------
__global__ void __launch_bounds__(256) k_l1(const float* __restrict__ b1) {
    __shared__ float4 sal[8][64];   // per-warp normalized alpha (all 4 heads)
    int w = (blockIdx.x * blockDim.x + threadIdx.x) >> 5;
    if (w >= NNODES) return;
    const int n = w, lane = threadIdx.x & 31, ws = (threadIdx.x >> 5);
    const int beg = g_rowptr[n], end = g_rowptr[n + 1];
    const int deg = end - beg;
    const float4 ad = *(const float4*)&g_adst1[n * 4];
    const int h = lane >> 3;
    float4 acc = make_float4(0, 0, 0, 0);

    if (deg <= 64) {
        int s0 = 0, s1 = 0;
        float4 e0 = make_float4(0, 0, 0, 0), e1 = e0;
        const int p0 = beg + lane, p1 = p0 + 32;
        const bool v0 = p0 < end, v1 = p1 < end;
        float4 mx = make_float4(-CUDART_INF_F, -CUDART_INF_F,
                                -CUDART_INF_F, -CUDART_INF_F);
        if (v0) {
            s0 = g_csrc[p0];
            e0 = lrelu4(make_float4(g_asrc1[s0 * 4 + 0] + ad.x,
                                    g_asrc1[s0 * 4 + 1] + ad.y,
                                    g_asrc1[s0 * 4 + 2] + ad.z,
                                    g_asrc1[s0 * 4 + 3] + ad.w));
            mx = max4(mx, e0);
        }
        if (v1) {
            s1 = g_csrc[p1];
            e1 = lrelu4(make_float4(g_asrc1[s1 * 4 + 0] + ad.x,
                                    g_asrc1[s1 * 4 + 1] + ad.y,
                                    g_asrc1[s1 * 4 + 2] + ad.z,
                                    g_asrc1[s1 * 4 + 3] + ad.w));
            mx = max4(mx, e1);
        }
        mx = wred_max4(mx);
        float4 sm = make_float4(0, 0, 0, 0);
        float4 x0 = make_float4(0, 0, 0, 0), x1 = x0;
        if (v0) { x0 = exp4(e0, mx); sm.x += x0.x; sm.y += x0.y; sm.z += x0.z; sm.w += x0.w; }
        if (v1) { x1 = exp4(e1, mx); sm.x += x1.x; sm.y += x1.y; sm.z += x1.z; sm.w += x1.w; }
        sm = wred_sum4(sm);
        float4 inv = make_float4(1.f / (sm.x + EPSV), 1.f / (sm.y + EPSV),
                                 1.f / (sm.z + EPSV), 1.f / (sm.w + EPSV));
        if (v0) sal[ws][lane] = make_float4(x0.x * inv.x, x0.y * inv.y,
                                            x0.z * inv.z, x0.w * inv.w);
        if (v1) sal[ws][lane + 32] = make_float4(x1.x * inv.x, x1.y * inv.y,
                                                 x1.z * inv.z, x1.w * inv.w);
        __syncwarp();
        for (int j = 0; j < deg; j++) {
            int sv = (j < 32) ? s0 : s1;
            int s = __shfl_sync(0xffffffffu, sv, j & 31);
            float alpha = ((const float*)&sal[ws][j])[h];
            float4 hv = *(const float4*)&g_h1[(size_t)s * F1 + lane * 4];
            acc.x = fmaf(hv.x, alpha, acc.x);
            acc.y = fmaf(hv.y, alpha, acc.y);
            acc.z = fmaf(hv.z, alpha, acc.z);
            acc.w = fmaf(hv.w, alpha, acc.w);
        }
    } else {
        // rare fallback via global ex buffer
        float4 mx = make_float4(-CUDART_INF_F, -CUDART_INF_F,
                                -CUDART_INF_F, -CUDART_INF_F);
        for (int p = beg + lane; p < end; p += 32) {
            int s = g_csrc[p];
            float4 e = lrelu4(make_float4(g_asrc1[s * 4 + 0] + ad.x,
                                          g_asrc1[s * 4 + 1] + ad.y,
                                          g_asrc1[s * 4 + 2] + ad.z,
                                          g_asrc1[s * 4 + 3] + ad.w));
            *(float4*)&g_ex1[(size_t)p * 4] = e;
            mx = max4(mx, e);
        }
        mx = wred_max4(mx);
        float4 sm = make_float4(0, 0, 0, 0);
        for (int p = beg + lane; p < end; p += 32) {
            float4 e = *(const float4*)&g_ex1[(size_t)p * 4];
            float4 ex = exp4(e, mx);
            *(float4*)&g_ex1[(size_t)p * 4] = ex;
            sm.x += ex.x; sm.y += ex.y; sm.z += ex.z; sm.w += ex.w;
        }
        sm = wred_sum4(sm);
        float4 inv = make_float4(1.f / (sm.x + EPSV), 1.f / (sm.y + EPSV),
                                 1.f / (sm.z + EPSV), 1.f / (sm.w + EPSV));
        __syncwarp();
        const float invh = (h == 0) ? inv.x : (h == 1) ? inv.y
                         : (h == 2) ? inv.z : inv.w;
        for (int p = beg; p < end; ++p) {
            int s = g_csrc[p];
            float alpha = g_ex1[(size_t)p * 4 + h] * invh;
            float4 hv = *(const float4*)&g_h1[(size_t)s * F1 + lane * 4];
            acc.x = fmaf(hv.x, alpha, acc.x);
            acc.y = fmaf(hv.y, alpha, acc.y);
            acc.z = fmaf(hv.z, alpha, acc.z);
            acc.w = fmaf(hv.w, alpha, acc.w);
        }
    }

    float4 b = *(const float4*)&b1[lane * 4];
    float4 v = make_float4(acc.x + b.x, acc.y + b.y, acc.z + b.z, acc.w + b.w);
    v.x = v.x > 0.f ? v.x : expm1f(v.x);
    v.y = v.y > 0.f ? v.y : expm1f(v.y);
    v.z = v.z > 0.f ? v.z : expm1f(v.z);
    v.w = v.w > 0.f ? v.w : expm1f(v.w);
    *(float4*)&g_agg1[(size_t)n * F1 + lane * 4] = v;
}

// ---------------- layer-2: fused softmax+aggregate, register-resident ---------
__global__ void __launch_bounds__(256) k_l2(const float* __restrict__ b2,
                                            float* __restrict__ out) {
    __shared__ float sal[8][64];
    int w = (blockIdx.x * blockDim.x + threadIdx.x) >> 5;
    if (w >= NNODES) return;
    const int n = w, lane = threadIdx.x & 31, ws = (threadIdx.x >> 5);
    const int beg = g_rowptr[n], end = g_rowptr[n + 1];
    const int deg = end - beg;
    const float adn = g_adst2[n];
    float2 acc = make_float2(0, 0);

    if (deg <= 64) {
        int s0 = 0, s1 = 0;
        float e0 = 0.f, e1 = 0.f;
        const int p0 = beg + lane, p1 = p0 + 32;
        const bool v0 = p0 < end, v1 = p1 < end;
        float mx = -CUDART_INF_F;
        if (v0) { s0 = g_csrc[p0]; e0 = lrelu(g_asrc2[s0] + adn); mx = fmaxf(mx, e0); }
        if (v1) { s1 = g_csrc[p1]; e1 = lrelu(g_asrc2[s1] + adn); mx = fmaxf(mx, e1); }
#pragma unroll
        for (int o = 16; o > 0; o >>= 1)
            mx = fmaxf(mx, __shfl_xor_sync(0xffffffffu, mx, o));
        float sm = 0.f, x0 = 0.f, x1 = 0.f;
        if (v0) { x0 = __expf(e0 - mx); sm += x0; }
        if (v1) { x1 = __expf(e1 - mx); sm += x1; }
#pragma unroll
        for (int o = 16; o > 0; o >>= 1) sm += __shfl_xor_sync(0xffffffffu, sm, o);
        float inv = 1.f / (sm + EPSV);
        if (v0) sal[ws][lane]      = x0 * inv;
        if (v1) sal[ws][lane + 32] = x1 * inv;
        __syncwarp();
        for (int j = 0; j < deg; j++) {
            int sv = (j < 32) ? s0 : s1;
            int s = __shfl_sync(0xffffffffu, sv, j & 31);
            float alpha = sal[ws][j];
            float2 hv = *(const float2*)&g_h2[(size_t)s * CO + lane * 2];
            acc.x = fmaf(hv.x, alpha, acc.x);
            acc.y = fmaf(hv.y, alpha, acc.y);
        }
    } else {
        float mx = -CUDART_INF_F;
        for (int p = beg + lane; p < end; p += 32) {
            int s = g_csrc[p];
            float e = lrelu(g_asrc2[s] + adn);
            g_ex2[p] = e;
            mx = fmaxf(mx, e);
        }
#pragma unroll
        for (int o = 16; o > 0; o >>= 1)
            mx = fmaxf(mx, __shfl_xor_sync(0xffffffffu, mx, o));
        float sm = 0.f;
        for (int p = beg + lane; p < end; p += 32) {
            float ex = __expf(g_ex2[p] - mx);
            g_ex2[p] = ex;
            sm += ex;
        }
#pragma unroll
        for (int o = 16; o > 0; o >>= 1) sm += __shfl_xor_sync(0xffffffffu, sm, o);
        float inv = 1.f / (sm + EPSV);
        __syncwarp();
        for (int p = beg; p < end; ++p) {
            int s = g_csrc[p];
            float alpha = g_ex2[p] * inv;
            float2 hv = *(const float2*)&g_h2[(size_t)s * CO + lane * 2];
            acc.x = fmaf(hv.x, alpha, acc.x);
            acc.y = fmaf(hv.y, alpha, acc.y);
        }
    }

    float2 b = *(const float2*)&b2[lane * 2];
    *(float2*)&out[(size_t)n * CO + lane * 2] = make_float2(acc.x + b.x, acc.y + b.y);
}

// ---------------- launcher -------------------------------------------------------
extern "C" void kernel_launch(void* const* d_in, const int* in_sizes, int n_in,
                              void* d_out, int out_size) {
    const float* x   = (const float*)d_in[0];
    const void*  ei  = d_in[1];
    const float* W1  = (const float*)d_in[2];
    const float* as1 = (const float*)d_in[3];
    const float* ad1 = (const float*)d_in[4];
    const float* b1  = (const float*)d_in[5];
    const float* W2  = (const float*)d_in[6];
    const float* as2 = (const float*)d_in[7];
    const float* ad2 = (const float*)d_in[8];
    const float* b2  = (const float*)d_in[9];
    float* out = (float*)d_out;

    (void)in_sizes; (void)n_in; (void)out_size;

    const int gNode  = (NNODES + TPB - 1) / TPB;
    const int gStats = (NNODES * NH1 + TPB - 1) / TPB;
    const int gEdge  = (ETOT + TPB - 1) / TPB;
    const int gWarp  = (int)(((long long)NNODES * 32 + TPB - 1) / TPB);

    // CSR build
    k_zero_deg<<<gNode, TPB>>>();
    k_prep<<<gEdge, TPB>>>(ei);
    k_scan1<<<NB1, SCAN_B>>>();
    k_scan2<<<1, 256>>>();
    k_scan3<<<gNode, TPB>>>();
    k_scatter<<<gEdge, TPB>>>();

    // layer 1
    gemm1_kernel<<<(NNODES + 127) / 128, 256>>>(x, W1);
    k_att1<<<gStats, TPB>>>(as1, ad1);
    k_l1<<<gWarp, TPB>>>(b1);

    // layer 2
    gemm2_kernel<<<(NNODES + 127) / 128, 256>>>(W2);
    k_att2<<<gNode, TPB>>>(as2, ad2);
    k_l2<<<gWarp, TPB>>>(b2, out);
}